// round 1
// baseline (speedup 1.0000x reference)
#include <cuda_runtime.h>
#include <math.h>

// Problem constants: B=2, S=1024 -> T=2048 tokens; D=768; E=8 experts; DFF=3072; top-2.
#define T    2048
#define D    768
#define E    8
#define DFF  3072

// GEMM tiling
#define BM 128
#define BN 128
#define BK 8
#define TM 8
#define TN 8
// 256 threads per CTA, each computes an 8x8 microtile of the 128x128 C tile.

// ---------------------------------------------------------------------------
// Device scratch (static globals; no runtime allocation anywhere)
// ---------------------------------------------------------------------------
__device__ int   g_cnt[E];            // tokens assigned per expert
__device__ int   g_tok[E * T];        // token id per compacted row (base e*T)
__device__ int   g_rowof[T * 2];      // global row index for (token, k)
__device__ float g_w[T * 2];          // gate weight for (token, k)
__device__ float g_H[(size_t)E * T * DFF];  // hidden activations (relu(x W1^T + b1))
__device__ float g_Y[(size_t)E * T * D];    // per-(token,expert) FFN outputs

// ---------------------------------------------------------------------------
// Reset per-expert counters (must run every launch; graph-capturable)
// ---------------------------------------------------------------------------
__global__ void reset_kernel() {
    if (threadIdx.x < E) g_cnt[threadIdx.x] = 0;
}

// ---------------------------------------------------------------------------
// Router: noisy top-k gating. One warp per token.
//   logits = x @ Wg^T + bg; nlog = x @ Wn^T + bn
//   noisy  = logits + noise * softplus(nlog)
//   top-2 -> softmax over the two selected values (others are exactly 0)
// Also compacts token ids into per-expert lists via atomic counters.
// Output values are position-invariant, so atomics do not affect determinism
// of the final result (combine reads by recorded row index).
// ---------------------------------------------------------------------------
__global__ void router_kernel(const float* __restrict__ x,
                              const float* __restrict__ noise,
                              const float* __restrict__ Wg,
                              const float* __restrict__ bg,
                              const float* __restrict__ Wn,
                              const float* __restrict__ bn)
{
    const int warp = (blockIdx.x * blockDim.x + threadIdx.x) >> 5;
    const int lane = threadIdx.x & 31;
    if (warp >= T) return;

    const float* xr = x + (size_t)warp * D;
    float xv[D / 32];
    #pragma unroll
    for (int i = 0; i < D / 32; i++) xv[i] = xr[lane + 32 * i];

    float nz[E];
    #pragma unroll
    for (int e = 0; e < E; e++) {
        const float* g  = Wg + e * D;
        const float* nw = Wn + e * D;
        float s1 = 0.f, s2 = 0.f;
        #pragma unroll
        for (int i = 0; i < D / 32; i++) {
            const float xi = xv[i];
            s1 = fmaf(xi, g[lane + 32 * i], s1);
            s2 = fmaf(xi, nw[lane + 32 * i], s2);
        }
        #pragma unroll
        for (int off = 16; off; off >>= 1) {
            s1 += __shfl_xor_sync(0xffffffffu, s1, off);
            s2 += __shfl_xor_sync(0xffffffffu, s2, off);
        }
        const float logit = s1 + bg[e];
        const float nlog  = s2 + bn[e];
        // stable softplus = logaddexp(nlog, 0)
        const float sp = fmaxf(nlog, 0.f) + log1pf(expf(-fabsf(nlog)));
        nz[e] = logit + noise[warp * E + e] * sp;
    }

    if (lane == 0) {
        int i0 = 0; float v0 = nz[0];
        #pragma unroll
        for (int e = 1; e < E; e++) if (nz[e] > v0) { v0 = nz[e]; i0 = e; }
        int i1 = -1; float v1 = -3.0e38f;
        #pragma unroll
        for (int e = 0; e < E; e++) if (e != i0 && nz[e] > v1) { v1 = nz[e]; i1 = e; }

        const float ex = expf(v1 - v0);          // v1 <= v0 -> safe
        const float inv = 1.f / (1.f + ex);
        const float w0 = inv;
        const float w1 = ex * inv;

        const int p0 = atomicAdd(&g_cnt[i0], 1);
        const int p1 = atomicAdd(&g_cnt[i1], 1);
        const int r0 = i0 * T + p0;
        const int r1 = i1 * T + p1;
        g_tok[r0] = warp;
        g_tok[r1] = warp;
        g_rowof[2 * warp]     = r0;
        g_rowof[2 * warp + 1] = r1;
        g_w[2 * warp]     = w0;
        g_w[2 * warp + 1] = w1;
    }
}

// ---------------------------------------------------------------------------
// Grouped GEMM (both operands K-major): C[m,n] = sum_k A[m,k] * W[e][n,k] + bias[e][n]
//   GATHER=true : A rows gathered from x via per-expert token list; C = g_H (+relu)
//   GATHER=false: A rows = g_H (already compacted per expert);       C = g_Y
// 128x128x8 tiles, 8x8 microtile, double-buffered smem, fp32.
// ---------------------------------------------------------------------------
template <bool GATHER, bool RELU>
__global__ __launch_bounds__(256, 2)
void gemm_kernel(const float* __restrict__ Asrc,
                 const float* __restrict__ W,
                 const float* __restrict__ bias,
                 const int N, const int K)
{
    const int e   = blockIdx.z;
    const int cnt = g_cnt[e];
    const int m0  = blockIdx.y * BM;
    if (m0 >= cnt) return;
    const int n0  = blockIdx.x * BN;

    __shared__ float As[2][BK][BM];
    __shared__ float Bs[2][BK][BN];

    const int tid  = threadIdx.x;
    const int arow = tid >> 1;            // 0..127
    const int ac4  = (tid & 1) * 4;       // 0 or 4

    // Resolve this thread's A source row (clamped for out-of-range rows).
    const float* Arow;
    {
        const int am = m0 + arow;
        if (GATHER) {
            const int tok = (am < cnt) ? g_tok[e * T + am] : 0;
            Arow = Asrc + (size_t)tok * K;
        } else {
            const int r = (am < cnt) ? am : 0;
            Arow = g_H + (size_t)e * T * K + (size_t)r * K;
        }
    }
    const float* Brow = W + (size_t)e * N * K + (size_t)(n0 + arow) * K;

    const int tx = tid & 15, ty = tid >> 4;
    const int mt = ty * TM, nt = tx * TN;

    float acc[TM][TN];
    #pragma unroll
    for (int i = 0; i < TM; i++)
        #pragma unroll
        for (int j = 0; j < TN; j++) acc[i][j] = 0.f;

    const int nk = K / BK;

    // Prologue: load tile 0
    float4 a4 = *reinterpret_cast<const float4*>(Arow + ac4);
    float4 b4 = *reinterpret_cast<const float4*>(Brow + ac4);
    As[0][ac4 + 0][arow] = a4.x; As[0][ac4 + 1][arow] = a4.y;
    As[0][ac4 + 2][arow] = a4.z; As[0][ac4 + 3][arow] = a4.w;
    Bs[0][ac4 + 0][arow] = b4.x; Bs[0][ac4 + 1][arow] = b4.y;
    Bs[0][ac4 + 2][arow] = b4.z; Bs[0][ac4 + 3][arow] = b4.w;
    __syncthreads();

    for (int kt = 0; kt < nk; kt++) {
        const int cur = kt & 1;
        const bool pf = (kt + 1 < nk);
        if (pf) {
            const int ko = (kt + 1) * BK;
            a4 = *reinterpret_cast<const float4*>(Arow + ko + ac4);
            b4 = *reinterpret_cast<const float4*>(Brow + ko + ac4);
        }
        #pragma unroll
        for (int kk = 0; kk < BK; kk++) {
            float ra[TM], rb[TN];
            #pragma unroll
            for (int i = 0; i < TM; i++) ra[i] = As[cur][kk][mt + i];
            #pragma unroll
            for (int j = 0; j < TN; j++) rb[j] = Bs[cur][kk][nt + j];
            #pragma unroll
            for (int i = 0; i < TM; i++)
                #pragma unroll
                for (int j = 0; j < TN; j++)
                    acc[i][j] = fmaf(ra[i], rb[j], acc[i][j]);
        }
        if (pf) {
            const int nb = cur ^ 1;
            As[nb][ac4 + 0][arow] = a4.x; As[nb][ac4 + 1][arow] = a4.y;
            As[nb][ac4 + 2][arow] = a4.z; As[nb][ac4 + 3][arow] = a4.w;
            Bs[nb][ac4 + 0][arow] = b4.x; Bs[nb][ac4 + 1][arow] = b4.y;
            Bs[nb][ac4 + 2][arow] = b4.z; Bs[nb][ac4 + 3][arow] = b4.w;
        }
        __syncthreads();
    }

    // Epilogue
    float* Cb = GATHER ? g_H : g_Y;
    float* Crow = Cb + (size_t)e * T * N;
    const float* be = bias + (size_t)e * N;
    #pragma unroll
    for (int i = 0; i < TM; i++) {
        const int m = m0 + mt + i;
        if (m < cnt) {
            float* cr = Crow + (size_t)m * N + n0 + nt;
            #pragma unroll
            for (int j = 0; j < TN; j++) {
                float v = acc[i][j] + be[n0 + nt + j];
                if (RELU) v = fmaxf(v, 0.f);
                cr[j] = v;
            }
        }
    }
}

// ---------------------------------------------------------------------------
// Combine: out[t] = w0 * Y[row0] + w1 * Y[row1]. Fully deterministic (no atomics).
// One block per token, 192 threads x float4 = 768 floats.
// ---------------------------------------------------------------------------
__global__ void combine_kernel(float* __restrict__ out)
{
    const int t = blockIdx.x;
    const int j = threadIdx.x;            // 0..191
    const int r0 = g_rowof[2 * t];
    const int r1 = g_rowof[2 * t + 1];
    const float w0 = g_w[2 * t];
    const float w1 = g_w[2 * t + 1];
    const float4 a = reinterpret_cast<const float4*>(g_Y + (size_t)r0 * D)[j];
    const float4 b = reinterpret_cast<const float4*>(g_Y + (size_t)r1 * D)[j];
    float4 o;
    o.x = fmaf(w0, a.x, w1 * b.x);
    o.y = fmaf(w0, a.y, w1 * b.y);
    o.z = fmaf(w0, a.z, w1 * b.z);
    o.w = fmaf(w0, a.w, w1 * b.w);
    reinterpret_cast<float4*>(out + (size_t)t * D)[j] = o;
}

// ---------------------------------------------------------------------------
// Launch
// ---------------------------------------------------------------------------
extern "C" void kernel_launch(void* const* d_in, const int* in_sizes, int n_in,
                              void* d_out, int out_size)
{
    const float* x     = (const float*)d_in[0];
    const float* noise = (const float*)d_in[1];
    const float* Wg    = (const float*)d_in[2];
    const float* bg    = (const float*)d_in[3];
    const float* Wn    = (const float*)d_in[4];
    const float* bn    = (const float*)d_in[5];
    const float* W1    = (const float*)d_in[6];
    const float* b1    = (const float*)d_in[7];
    const float* W2    = (const float*)d_in[8];
    const float* b2    = (const float*)d_in[9];
    float* out = (float*)d_out;

    reset_kernel<<<1, 32>>>();
    router_kernel<<<T / 8, 256>>>(x, noise, Wg, bg, Wn, bn);

    // GEMM1: H = relu(x_gathered @ W1[e]^T + b1[e])  -- M<=2048/expert, N=3072, K=768
    {
        dim3 grid(DFF / BN, T / BM, E);
        gemm_kernel<true, true><<<grid, 256>>>(x, W1, b1, DFF, D);
    }
    // GEMM2: Y = H @ W2[e]^T + b2[e]                 -- N=768, K=3072
    {
        dim3 grid(D / BN, T / BM, E);
        gemm_kernel<false, false><<<grid, 256>>>(nullptr, W2, b2, D, DFF);
    }

    combine_kernel<<<T, D / 4>>>(out);
}

// round 2
// speedup vs baseline: 2.0443x; 2.0443x over previous
#include <cuda_runtime.h>
#include <math.h>
#include <stdint.h>

// Problem constants: B=2, S=1024 -> T=2048 tokens; D=768; E=8 experts; DFF=3072; top-2.
#define T    2048
#define D    768
#define E    8
#define DFF  3072

// GEMM tiling: 128x128 CTA tile, BK=16, 8 warps (2x4), 64x32 warp tile,
// tf32 mma.sync m16n8k8 (4x4 mma grid per warp per k-step).
#define BM 128
#define BN 128
#define BK 16
#define SPAD 20   // smem row stride in elems (16 + 4 pad -> conflict-free frags)

// ---------------------------------------------------------------------------
// Device scratch
// ---------------------------------------------------------------------------
__device__ int   g_cnt[E];
__device__ int   g_tok[E * T];
__device__ int   g_rowof[T * 2];
__device__ float g_w[T * 2];
__device__ float g_H[(size_t)E * T * DFF];
__device__ float g_Y[(size_t)E * T * D];

__global__ void reset_kernel() {
    if (threadIdx.x < E) g_cnt[threadIdx.x] = 0;
}

// ---------------------------------------------------------------------------
// Router (unchanged from R1): one warp per token, noisy top-2 gating +
// atomic per-expert compaction. Values are position-invariant so the final
// output is deterministic.
// ---------------------------------------------------------------------------
__global__ void router_kernel(const float* __restrict__ x,
                              const float* __restrict__ noise,
                              const float* __restrict__ Wg,
                              const float* __restrict__ bg,
                              const float* __restrict__ Wn,
                              const float* __restrict__ bn)
{
    const int warp = (blockIdx.x * blockDim.x + threadIdx.x) >> 5;
    const int lane = threadIdx.x & 31;
    if (warp >= T) return;

    const float* xr = x + (size_t)warp * D;
    float xv[D / 32];
    #pragma unroll
    for (int i = 0; i < D / 32; i++) xv[i] = xr[lane + 32 * i];

    float nz[E];
    #pragma unroll
    for (int e = 0; e < E; e++) {
        const float* g  = Wg + e * D;
        const float* nw = Wn + e * D;
        float s1 = 0.f, s2 = 0.f;
        #pragma unroll
        for (int i = 0; i < D / 32; i++) {
            const float xi = xv[i];
            s1 = fmaf(xi, g[lane + 32 * i], s1);
            s2 = fmaf(xi, nw[lane + 32 * i], s2);
        }
        #pragma unroll
        for (int off = 16; off; off >>= 1) {
            s1 += __shfl_xor_sync(0xffffffffu, s1, off);
            s2 += __shfl_xor_sync(0xffffffffu, s2, off);
        }
        const float logit = s1 + bg[e];
        const float nlog  = s2 + bn[e];
        const float sp = fmaxf(nlog, 0.f) + log1pf(expf(-fabsf(nlog)));
        nz[e] = logit + noise[warp * E + e] * sp;
    }

    if (lane == 0) {
        int i0 = 0; float v0 = nz[0];
        #pragma unroll
        for (int e = 1; e < E; e++) if (nz[e] > v0) { v0 = nz[e]; i0 = e; }
        int i1 = -1; float v1 = -3.0e38f;
        #pragma unroll
        for (int e = 0; e < E; e++) if (e != i0 && nz[e] > v1) { v1 = nz[e]; i1 = e; }

        const float ex = expf(v1 - v0);
        const float inv = 1.f / (1.f + ex);

        const int p0 = atomicAdd(&g_cnt[i0], 1);
        const int p1 = atomicAdd(&g_cnt[i1], 1);
        const int r0 = i0 * T + p0;
        const int r1 = i1 * T + p1;
        g_tok[r0] = warp;
        g_tok[r1] = warp;
        g_rowof[2 * warp]     = r0;
        g_rowof[2 * warp + 1] = r1;
        g_w[2 * warp]     = inv;
        g_w[2 * warp + 1] = ex * inv;
    }
}

// ---------------------------------------------------------------------------
// tf32 helpers
// ---------------------------------------------------------------------------
__device__ __forceinline__ uint32_t f2tf32(float x) {
    uint32_t u;
    asm("cvt.rna.tf32.f32 %0, %1;" : "=r"(u) : "f"(x));
    return u;
}

__device__ __forceinline__ void mma_tf32(float& c0, float& c1, float& c2, float& c3,
                                         uint32_t a0, uint32_t a1, uint32_t a2, uint32_t a3,
                                         uint32_t b0, uint32_t b1)
{
    asm volatile(
        "mma.sync.aligned.m16n8k8.row.col.f32.tf32.tf32.f32 "
        "{%0,%1,%2,%3}, {%4,%5,%6,%7}, {%8,%9}, {%0,%1,%2,%3};"
        : "+f"(c0), "+f"(c1), "+f"(c2), "+f"(c3)
        : "r"(a0), "r"(a1), "r"(a2), "r"(a3), "r"(b0), "r"(b1));
}

// ---------------------------------------------------------------------------
// Grouped tf32 tensor-core GEMM.
//   C[m,n] = sum_k A[m,k] * W[e][n,k] + bias[e][n]   (both K-contiguous)
//   GATHER: A rows gathered from x via token list; output g_H with relu
//   else:   A rows from g_H (compacted);             output g_Y
// ---------------------------------------------------------------------------
template <bool GATHER, bool RELU>
__global__ __launch_bounds__(256, 2)
void gemm_tc_kernel(const float* __restrict__ Asrc,
                    const float* __restrict__ W,
                    const float* __restrict__ bias,
                    const int N, const int K)
{
    const int e   = blockIdx.z;
    const int cnt = g_cnt[e];
    const int m0  = blockIdx.y * BM;
    if (m0 >= cnt) return;
    const int n0  = blockIdx.x * BN;

    __shared__ uint32_t As[2][BM][SPAD];
    __shared__ uint32_t Bs[2][BN][SPAD];

    const int tid  = threadIdx.x;
    const int lane = tid & 31;
    const int warp = tid >> 5;
    const int wm   = warp >> 2;        // 0..1  -> warp row (64 rows)
    const int wn   = warp & 3;         // 0..3  -> warp col (32 cols)
    const int g    = lane >> 2;        // group id 0..7
    const int qq   = lane & 3;         // quad pos 0..3

    // --- global load mapping: 128 rows x 16 cols per operand, 2 float4/thread
    const int lrow = tid >> 1;         // 0..127
    const int lcg  = (tid & 1) * 4;    // 0 or 4  (+8 for second float4)

    const float* Arow;
    {
        const int am = m0 + lrow;
        if (GATHER) {
            const int tok = (am < cnt) ? g_tok[e * T + am] : 0;
            Arow = Asrc + (size_t)tok * K;
        } else {
            const int r = (am < cnt) ? am : 0;
            Arow = g_H + (size_t)e * T * K + (size_t)r * K;
        }
    }
    const float* Brow = W + (size_t)e * N * K + (size_t)(n0 + lrow) * K;

    float acc[4][4][4];
    #pragma unroll
    for (int mi = 0; mi < 4; mi++)
        #pragma unroll
        for (int ni = 0; ni < 4; ni++)
            #pragma unroll
            for (int r = 0; r < 4; r++) acc[mi][ni][r] = 0.f;

    const int nk = K / BK;

    // Prologue: stage tile 0
    float4 fa0 = *reinterpret_cast<const float4*>(Arow + lcg);
    float4 fa1 = *reinterpret_cast<const float4*>(Arow + lcg + 8);
    float4 fb0 = *reinterpret_cast<const float4*>(Brow + lcg);
    float4 fb1 = *reinterpret_cast<const float4*>(Brow + lcg + 8);
    {
        uint32_t* ap = &As[0][lrow][lcg];
        ap[0] = f2tf32(fa0.x); ap[1] = f2tf32(fa0.y); ap[2] = f2tf32(fa0.z); ap[3] = f2tf32(fa0.w);
        ap[8] = f2tf32(fa1.x); ap[9] = f2tf32(fa1.y); ap[10] = f2tf32(fa1.z); ap[11] = f2tf32(fa1.w);
        uint32_t* bp = &Bs[0][lrow][lcg];
        bp[0] = f2tf32(fb0.x); bp[1] = f2tf32(fb0.y); bp[2] = f2tf32(fb0.z); bp[3] = f2tf32(fb0.w);
        bp[8] = f2tf32(fb1.x); bp[9] = f2tf32(fb1.y); bp[10] = f2tf32(fb1.z); bp[11] = f2tf32(fb1.w);
    }
    __syncthreads();

    for (int kt = 0; kt < nk; kt++) {
        const int cur = kt & 1;
        const bool pf = (kt + 1 < nk);
        if (pf) {
            const int ko = (kt + 1) * BK;
            fa0 = *reinterpret_cast<const float4*>(Arow + ko + lcg);
            fa1 = *reinterpret_cast<const float4*>(Arow + ko + lcg + 8);
            fb0 = *reinterpret_cast<const float4*>(Brow + ko + lcg);
            fb1 = *reinterpret_cast<const float4*>(Brow + ko + lcg + 8);
        }

        // compute on buffer `cur`: 2 k-steps of 8
        #pragma unroll
        for (int ks = 0; ks < 2; ks++) {
            const int k0 = ks * 8;
            uint32_t af[4][4], bf[4][2];
            #pragma unroll
            for (int mi = 0; mi < 4; mi++) {
                const int r = wm * 64 + mi * 16 + g;
                af[mi][0] = As[cur][r    ][k0 + qq];
                af[mi][1] = As[cur][r + 8][k0 + qq];
                af[mi][2] = As[cur][r    ][k0 + qq + 4];
                af[mi][3] = As[cur][r + 8][k0 + qq + 4];
            }
            #pragma unroll
            for (int ni = 0; ni < 4; ni++) {
                const int n = wn * 32 + ni * 8 + g;
                bf[ni][0] = Bs[cur][n][k0 + qq];
                bf[ni][1] = Bs[cur][n][k0 + qq + 4];
            }
            #pragma unroll
            for (int mi = 0; mi < 4; mi++)
                #pragma unroll
                for (int ni = 0; ni < 4; ni++)
                    mma_tf32(acc[mi][ni][0], acc[mi][ni][1], acc[mi][ni][2], acc[mi][ni][3],
                             af[mi][0], af[mi][1], af[mi][2], af[mi][3],
                             bf[ni][0], bf[ni][1]);
        }

        if (pf) {
            const int nb = cur ^ 1;
            uint32_t* ap = &As[nb][lrow][lcg];
            ap[0] = f2tf32(fa0.x); ap[1] = f2tf32(fa0.y); ap[2] = f2tf32(fa0.z); ap[3] = f2tf32(fa0.w);
            ap[8] = f2tf32(fa1.x); ap[9] = f2tf32(fa1.y); ap[10] = f2tf32(fa1.z); ap[11] = f2tf32(fa1.w);
            uint32_t* bp = &Bs[nb][lrow][lcg];
            bp[0] = f2tf32(fb0.x); bp[1] = f2tf32(fb0.y); bp[2] = f2tf32(fb0.z); bp[3] = f2tf32(fb0.w);
            bp[8] = f2tf32(fb1.x); bp[9] = f2tf32(fb1.y); bp[10] = f2tf32(fb1.z); bp[11] = f2tf32(fb1.w);
        }
        __syncthreads();
    }

    // ---- epilogue ----
    float* Cb = GATHER ? g_H : g_Y;
    float* Cbase = Cb + (size_t)e * T * N;
    const float* be = bias + (size_t)e * N;

    #pragma unroll
    for (int mi = 0; mi < 4; mi++) {
        #pragma unroll
        for (int half = 0; half < 2; half++) {
            const int m = m0 + wm * 64 + mi * 16 + g + half * 8;
            if (m < cnt) {
                float* cr = Cbase + (size_t)m * N;
                #pragma unroll
                for (int ni = 0; ni < 4; ni++) {
                    const int c = n0 + wn * 32 + ni * 8 + 2 * qq;
                    float v0 = acc[mi][ni][2 * half]     + be[c];
                    float v1 = acc[mi][ni][2 * half + 1] + be[c + 1];
                    if (RELU) { v0 = fmaxf(v0, 0.f); v1 = fmaxf(v1, 0.f); }
                    reinterpret_cast<float2*>(cr + c)[0] = make_float2(v0, v1);
                }
            }
        }
    }
}

// ---------------------------------------------------------------------------
// Combine (deterministic): out[t] = w0*Y[row0] + w1*Y[row1]
// ---------------------------------------------------------------------------
__global__ void combine_kernel(float* __restrict__ out)
{
    const int t = blockIdx.x;
    const int j = threadIdx.x;            // 0..191
    const int r0 = g_rowof[2 * t];
    const int r1 = g_rowof[2 * t + 1];
    const float w0 = g_w[2 * t];
    const float w1 = g_w[2 * t + 1];
    const float4 a = reinterpret_cast<const float4*>(g_Y + (size_t)r0 * D)[j];
    const float4 b = reinterpret_cast<const float4*>(g_Y + (size_t)r1 * D)[j];
    float4 o;
    o.x = fmaf(w0, a.x, w1 * b.x);
    o.y = fmaf(w0, a.y, w1 * b.y);
    o.z = fmaf(w0, a.z, w1 * b.z);
    o.w = fmaf(w0, a.w, w1 * b.w);
    reinterpret_cast<float4*>(out + (size_t)t * D)[j] = o;
}

// ---------------------------------------------------------------------------
// Launch
// ---------------------------------------------------------------------------
extern "C" void kernel_launch(void* const* d_in, const int* in_sizes, int n_in,
                              void* d_out, int out_size)
{
    const float* x     = (const float*)d_in[0];
    const float* noise = (const float*)d_in[1];
    const float* Wg    = (const float*)d_in[2];
    const float* bg    = (const float*)d_in[3];
    const float* Wn    = (const float*)d_in[4];
    const float* bn    = (const float*)d_in[5];
    const float* W1    = (const float*)d_in[6];
    const float* b1    = (const float*)d_in[7];
    const float* W2    = (const float*)d_in[8];
    const float* b2    = (const float*)d_in[9];
    float* out = (float*)d_out;

    reset_kernel<<<1, 32>>>();
    router_kernel<<<T / 8, 256>>>(x, noise, Wg, bg, Wn, bn);

    // GEMM1: H = relu(x_gathered @ W1[e]^T + b1[e])  N=3072, K=768
    {
        dim3 grid(DFF / BN, T / BM, E);
        gemm_tc_kernel<true, true><<<grid, 256>>>(x, W1, b1, DFF, D);
    }
    // GEMM2: Y = H @ W2[e]^T + b2[e]                 N=768, K=3072
    {
        dim3 grid(D / BN, T / BM, E);
        gemm_tc_kernel<false, false><<<grid, 256>>>(nullptr, W2, b2, D, DFF);
    }

    combine_kernel<<<T, D / 4>>>(out);
}

// round 3
// speedup vs baseline: 3.5012x; 1.7127x over previous
#include <cuda_runtime.h>
#include <cuda_fp16.h>
#include <math.h>
#include <stdint.h>

// Problem constants: B=2, S=1024 -> T=2048 tokens; D=768; E=8 experts; DFF=3072; top-2.
#define T    2048
#define D    768
#define E    8
#define DFF  3072

// GEMM tiling: 128x128 CTA tile, BK=16, 8 warps (2x4), 64x32 warp tile,
// fp16 mma.sync m16n8k16 with ldmatrix fragment loads.
#define BM 128
#define BN 128
#define BK 16
#define SA 24      // smem row stride in halves (16 + 8 pad): ldmatrix conflict-free

// ---------------------------------------------------------------------------
// Device scratch
// ---------------------------------------------------------------------------
__device__ int    g_cnt[E];
__device__ int    g_tok[E * T];
__device__ int    g_rowof[T * 2];
__device__ float  g_w[T * 2];
__device__ __half g_Hh[(size_t)E * T * DFF];      // hidden acts, fp16
__device__ float  g_Y[2][E * T * D];              // split-K partial outputs

__global__ void reset_kernel() {
    if (threadIdx.x < E) g_cnt[threadIdx.x] = 0;
}

// ---------------------------------------------------------------------------
// Router: one warp per token, noisy top-2 gating + atomic per-expert
// compaction. Row values are position-invariant -> deterministic output.
// ---------------------------------------------------------------------------
__global__ void router_kernel(const float* __restrict__ x,
                              const float* __restrict__ noise,
                              const float* __restrict__ Wg,
                              const float* __restrict__ bg,
                              const float* __restrict__ Wn,
                              const float* __restrict__ bn)
{
    const int warp = (blockIdx.x * blockDim.x + threadIdx.x) >> 5;
    const int lane = threadIdx.x & 31;
    if (warp >= T) return;

    const float* xr = x + (size_t)warp * D;
    float xv[D / 32];
    #pragma unroll
    for (int i = 0; i < D / 32; i++) xv[i] = xr[lane + 32 * i];

    float nz[E];
    #pragma unroll
    for (int e = 0; e < E; e++) {
        const float* g  = Wg + e * D;
        const float* nw = Wn + e * D;
        float s1 = 0.f, s2 = 0.f;
        #pragma unroll
        for (int i = 0; i < D / 32; i++) {
            const float xi = xv[i];
            s1 = fmaf(xi, g[lane + 32 * i], s1);
            s2 = fmaf(xi, nw[lane + 32 * i], s2);
        }
        #pragma unroll
        for (int off = 16; off; off >>= 1) {
            s1 += __shfl_xor_sync(0xffffffffu, s1, off);
            s2 += __shfl_xor_sync(0xffffffffu, s2, off);
        }
        const float logit = s1 + bg[e];
        const float nlog  = s2 + bn[e];
        const float sp = fmaxf(nlog, 0.f) + log1pf(expf(-fabsf(nlog)));
        nz[e] = logit + noise[warp * E + e] * sp;
    }

    if (lane == 0) {
        int i0 = 0; float v0 = nz[0];
        #pragma unroll
        for (int e = 1; e < E; e++) if (nz[e] > v0) { v0 = nz[e]; i0 = e; }
        int i1 = -1; float v1 = -3.0e38f;
        #pragma unroll
        for (int e = 0; e < E; e++) if (e != i0 && nz[e] > v1) { v1 = nz[e]; i1 = e; }

        const float ex = expf(v1 - v0);
        const float inv = 1.f / (1.f + ex);

        const int p0 = atomicAdd(&g_cnt[i0], 1);
        const int p1 = atomicAdd(&g_cnt[i1], 1);
        const int r0 = i0 * T + p0;
        const int r1 = i1 * T + p1;
        g_tok[r0] = warp;
        g_tok[r1] = warp;
        g_rowof[2 * warp]     = r0;
        g_rowof[2 * warp + 1] = r1;
        g_w[2 * warp]     = inv;
        g_w[2 * warp + 1] = ex * inv;
    }
}

// ---------------------------------------------------------------------------
// helpers
// ---------------------------------------------------------------------------
__device__ __forceinline__ uint32_t smem_u32(const void* p) {
    return (uint32_t)__cvta_generic_to_shared(p);
}

__device__ __forceinline__ uint4 pack8(float4 a, float4 b) {
    __half2 h0 = __floats2half2_rn(a.x, a.y);
    __half2 h1 = __floats2half2_rn(a.z, a.w);
    __half2 h2 = __floats2half2_rn(b.x, b.y);
    __half2 h3 = __floats2half2_rn(b.z, b.w);
    uint4 u;
    u.x = *reinterpret_cast<uint32_t*>(&h0);
    u.y = *reinterpret_cast<uint32_t*>(&h1);
    u.z = *reinterpret_cast<uint32_t*>(&h2);
    u.w = *reinterpret_cast<uint32_t*>(&h3);
    return u;
}

__device__ __forceinline__ void ldsm4(uint32_t& r0, uint32_t& r1, uint32_t& r2, uint32_t& r3,
                                      uint32_t addr) {
    asm volatile("ldmatrix.sync.aligned.m8n8.x4.shared.b16 {%0,%1,%2,%3}, [%4];"
                 : "=r"(r0), "=r"(r1), "=r"(r2), "=r"(r3) : "r"(addr));
}

__device__ __forceinline__ void mma_f16(float& c0, float& c1, float& c2, float& c3,
                                        uint32_t a0, uint32_t a1, uint32_t a2, uint32_t a3,
                                        uint32_t b0, uint32_t b1) {
    asm volatile(
        "mma.sync.aligned.m16n8k16.row.col.f32.f16.f16.f32 "
        "{%0,%1,%2,%3}, {%4,%5,%6,%7}, {%8,%9}, {%0,%1,%2,%3};"
        : "+f"(c0), "+f"(c1), "+f"(c2), "+f"(c3)
        : "r"(a0), "r"(a1), "r"(a2), "r"(a3), "r"(b0), "r"(b1));
}

// ---------------------------------------------------------------------------
// Grouped fp16 tensor-core GEMM.
//   MODE 0: H = relu(gather(x) @ W1[e]^T + b1[e]); A fp32 gathered, C -> g_Hh (fp16)
//   MODE 1: Y = H @ W2[e]^T (+ b2[e] on split 0);  A fp16 from g_Hh, split-K=2,
//           C -> g_Y[split] (fp32)
// ---------------------------------------------------------------------------
template <int MODE>
__global__ __launch_bounds__(256, 2)
void gemm_f16_kernel(const float* __restrict__ Asrc,
                     const float* __restrict__ W,
                     const float* __restrict__ bias,
                     const int N, const int Ktot)
{
    int e, s, k0, Klen;
    if (MODE == 0) { e = blockIdx.z; s = 0; k0 = 0; Klen = Ktot; }
    else           { e = blockIdx.z & (E - 1); s = blockIdx.z >> 3; Klen = Ktot >> 1; k0 = s * Klen; }

    const int cnt = g_cnt[e];
    const int m0  = blockIdx.y * BM;
    if (m0 >= cnt) return;
    const int n0  = blockIdx.x * BN;

    __shared__ __half As[2][BM][SA];
    __shared__ __half Bs[2][BN][SA];

    const int tid  = threadIdx.x;
    const int lane = tid & 31;
    const int warp = tid >> 5;
    const int wm   = warp >> 2;        // 0..1
    const int wn   = warp & 3;         // 0..3
    const int g    = lane >> 2;
    const int q    = lane & 3;

    // global staging mapping: 128 rows x 16 cols, 8 elems/thread
    const int lrow = tid >> 1;
    const int cg   = (tid & 1) * 8;

    const float*  Arow_f = nullptr;
    const __half* Arow_h = nullptr;
    {
        const int am = m0 + lrow;
        if (MODE == 0) {
            const int tok = (am < cnt) ? g_tok[e * T + am] : 0;
            Arow_f = Asrc + (size_t)tok * Ktot;
        } else {
            const int r = (am < cnt) ? am : 0;
            Arow_h = g_Hh + ((size_t)e * T + r) * Ktot + k0;
        }
    }
    const float* Brow = W + (size_t)e * N * Ktot + (size_t)(n0 + lrow) * Ktot + k0;

    // ldmatrix lane base addresses (buffer 0)
    uint32_t aAddr[4], bAddr[2];
    {
        const int rin = lane & 15;
        const int ch  = lane >> 4;
        #pragma unroll
        for (int mi = 0; mi < 4; mi++)
            aAddr[mi] = smem_u32(&As[0][wm * 64 + mi * 16 + rin][ch * 8]);
    }
    {
        const int rin = ((lane >> 4) << 3) + (lane & 7);
        const int ch  = (lane >> 3) & 1;
        #pragma unroll
        for (int p = 0; p < 2; p++)
            bAddr[p] = smem_u32(&Bs[0][wn * 32 + p * 16 + rin][ch * 8]);
    }
    const uint32_t bufOff = BM * SA * sizeof(__half);

    float acc[4][4][4];
    #pragma unroll
    for (int mi = 0; mi < 4; mi++)
        #pragma unroll
        for (int ni = 0; ni < 4; ni++)
            #pragma unroll
            for (int r = 0; r < 4; r++) acc[mi][ni][r] = 0.f;

    const int nk = Klen / BK;

    // prologue
    float4 fb0 = *reinterpret_cast<const float4*>(Brow + cg);
    float4 fb1 = *reinterpret_cast<const float4*>(Brow + cg + 4);
    float4 fa0, fa1; uint4 ha;
    if (MODE == 0) {
        fa0 = *reinterpret_cast<const float4*>(Arow_f + cg);
        fa1 = *reinterpret_cast<const float4*>(Arow_f + cg + 4);
    } else {
        ha = *reinterpret_cast<const uint4*>(Arow_h + cg);
    }
    *reinterpret_cast<uint4*>(&As[0][lrow][cg]) = (MODE == 0) ? pack8(fa0, fa1) : ha;
    *reinterpret_cast<uint4*>(&Bs[0][lrow][cg]) = pack8(fb0, fb1);
    __syncthreads();

    for (int kt = 0; kt < nk; kt++) {
        const int  cur = kt & 1;
        const bool pf  = (kt + 1 < nk);
        if (pf) {
            const int ko = (kt + 1) * BK;
            fb0 = *reinterpret_cast<const float4*>(Brow + ko + cg);
            fb1 = *reinterpret_cast<const float4*>(Brow + ko + cg + 4);
            if (MODE == 0) {
                fa0 = *reinterpret_cast<const float4*>(Arow_f + ko + cg);
                fa1 = *reinterpret_cast<const float4*>(Arow_f + ko + cg + 4);
            } else {
                ha = *reinterpret_cast<const uint4*>(Arow_h + ko + cg);
            }
        }

        const uint32_t off = cur ? bufOff : 0u;
        uint32_t af[4][4], bf[4][2];
        #pragma unroll
        for (int mi = 0; mi < 4; mi++)
            ldsm4(af[mi][0], af[mi][1], af[mi][2], af[mi][3], aAddr[mi] + off);
        #pragma unroll
        for (int p = 0; p < 2; p++) {
            uint32_t r0, r1, r2, r3;
            ldsm4(r0, r1, r2, r3, bAddr[p] + off);
            bf[2 * p][0] = r0; bf[2 * p][1] = r1;
            bf[2 * p + 1][0] = r2; bf[2 * p + 1][1] = r3;
        }
        #pragma unroll
        for (int mi = 0; mi < 4; mi++)
            #pragma unroll
            for (int ni = 0; ni < 4; ni++)
                mma_f16(acc[mi][ni][0], acc[mi][ni][1], acc[mi][ni][2], acc[mi][ni][3],
                        af[mi][0], af[mi][1], af[mi][2], af[mi][3],
                        bf[ni][0], bf[ni][1]);

        if (pf) {
            const int nb = cur ^ 1;
            *reinterpret_cast<uint4*>(&As[nb][lrow][cg]) = (MODE == 0) ? pack8(fa0, fa1) : ha;
            *reinterpret_cast<uint4*>(&Bs[nb][lrow][cg]) = pack8(fb0, fb1);
        }
        __syncthreads();
    }

    // ---- epilogue ----
    const float* be = bias + (size_t)e * N;
    if (MODE == 0) {
        __half* Cb = g_Hh + (size_t)e * T * N;
        #pragma unroll
        for (int mi = 0; mi < 4; mi++) {
            #pragma unroll
            for (int hh = 0; hh < 2; hh++) {
                const int m = m0 + wm * 64 + mi * 16 + g + hh * 8;
                if (m < cnt) {
                    __half* cr = Cb + (size_t)m * N;
                    #pragma unroll
                    for (int ni = 0; ni < 4; ni++) {
                        const int c = n0 + wn * 32 + ni * 8 + 2 * q;
                        float v0 = acc[mi][ni][2 * hh]     + be[c];
                        float v1 = acc[mi][ni][2 * hh + 1] + be[c + 1];
                        v0 = fmaxf(v0, 0.f); v1 = fmaxf(v1, 0.f);
                        *reinterpret_cast<__half2*>(cr + c) = __floats2half2_rn(v0, v1);
                    }
                }
            }
        }
    } else {
        float* Cb = g_Y[s] + (size_t)e * T * N;
        #pragma unroll
        for (int mi = 0; mi < 4; mi++) {
            #pragma unroll
            for (int hh = 0; hh < 2; hh++) {
                const int m = m0 + wm * 64 + mi * 16 + g + hh * 8;
                if (m < cnt) {
                    float* cr = Cb + (size_t)m * N;
                    #pragma unroll
                    for (int ni = 0; ni < 4; ni++) {
                        const int c = n0 + wn * 32 + ni * 8 + 2 * q;
                        float v0 = acc[mi][ni][2 * hh];
                        float v1 = acc[mi][ni][2 * hh + 1];
                        if (s == 0) { v0 += be[c]; v1 += be[c + 1]; }
                        *reinterpret_cast<float2*>(cr + c) = make_float2(v0, v1);
                    }
                }
            }
        }
    }
}

// ---------------------------------------------------------------------------
// Combine (deterministic): out[t] = w0*(Y0[r0]+Y1[r0]) + w1*(Y0[r1]+Y1[r1])
// ---------------------------------------------------------------------------
__global__ void combine_kernel(float* __restrict__ out)
{
    const int t = blockIdx.x;
    const int j = threadIdx.x;            // 0..191
    const int r0 = g_rowof[2 * t];
    const int r1 = g_rowof[2 * t + 1];
    const float w0 = g_w[2 * t];
    const float w1 = g_w[2 * t + 1];
    const float4 a0 = reinterpret_cast<const float4*>(g_Y[0] + (size_t)r0 * D)[j];
    const float4 a1 = reinterpret_cast<const float4*>(g_Y[1] + (size_t)r0 * D)[j];
    const float4 b0 = reinterpret_cast<const float4*>(g_Y[0] + (size_t)r1 * D)[j];
    const float4 b1 = reinterpret_cast<const float4*>(g_Y[1] + (size_t)r1 * D)[j];
    float4 o;
    o.x = fmaf(w0, a0.x + a1.x, w1 * (b0.x + b1.x));
    o.y = fmaf(w0, a0.y + a1.y, w1 * (b0.y + b1.y));
    o.z = fmaf(w0, a0.z + a1.z, w1 * (b0.z + b1.z));
    o.w = fmaf(w0, a0.w + a1.w, w1 * (b0.w + b1.w));
    reinterpret_cast<float4*>(out + (size_t)t * D)[j] = o;
}

// ---------------------------------------------------------------------------
// Launch
// ---------------------------------------------------------------------------
extern "C" void kernel_launch(void* const* d_in, const int* in_sizes, int n_in,
                              void* d_out, int out_size)
{
    const float* x     = (const float*)d_in[0];
    const float* noise = (const float*)d_in[1];
    const float* Wg    = (const float*)d_in[2];
    const float* bg    = (const float*)d_in[3];
    const float* Wn    = (const float*)d_in[4];
    const float* bn    = (const float*)d_in[5];
    const float* W1    = (const float*)d_in[6];
    const float* b1    = (const float*)d_in[7];
    const float* W2    = (const float*)d_in[8];
    const float* b2    = (const float*)d_in[9];
    float* out = (float*)d_out;

    reset_kernel<<<1, 32>>>();
    router_kernel<<<T / 8, 256>>>(x, noise, Wg, bg, Wn, bn);

    // GEMM1: H = relu(x_gathered @ W1[e]^T + b1[e])  N=3072, K=768
    {
        dim3 grid(DFF / BN, T / BM, E);
        gemm_f16_kernel<0><<<grid, 256>>>(x, W1, b1, DFF, D);
    }
    // GEMM2: Y = H @ W2[e]^T + b2[e], split-K=2      N=768, K=3072
    {
        dim3 grid(D / BN, T / BM, 2 * E);
        gemm_f16_kernel<1><<<grid, 256>>>(nullptr, W2, b2, D, DFF);
    }

    combine_kernel<<<T, D / 4>>>(out);
}

// round 5
// speedup vs baseline: 4.2307x; 1.2084x over previous
#include <cuda_runtime.h>
#include <cuda_fp16.h>
#include <math.h>
#include <stdint.h>

// Problem constants: B=2, S=1024 -> T=2048 tokens; D=768; E=8 experts; DFF=3072; top-2.
#define T    2048
#define D    768
#define E    8
#define DFF  3072

// GEMM tiling: 128x128 CTA tile, BK=16, 8 warps (2x4), 64x32 warp tiles,
// fp16 mma.sync m16n8k16 + ldmatrix, 4-stage cp.async pipeline.
#define BM 128
#define BN 128
#define BK 16
#define SA 24            // smem row stride (halves): 16 + 8 pad, ldmatrix conflict-free
#define STAGES 4
#define STG_BYTES (BM * SA * 2)   // 6144 B per operand per stage

// ---------------------------------------------------------------------------
// Device scratch
// ---------------------------------------------------------------------------
__device__ int    g_cnt[E];
__device__ int    g_tok[E * T];
__device__ int    g_rowof[T * 2];
__device__ float  g_w[T * 2];
__device__ __half g_xh[T * D];                    // x in fp16
__device__ __half g_W1h[(size_t)E * DFF * D];     // W1 in fp16
__device__ __half g_W2h[(size_t)E * D * DFF];     // W2 in fp16
__device__ __half g_Hh[(size_t)E * T * DFF];      // hidden acts, fp16
__device__ float  g_Y[2][E * T * D];              // split-K partial outputs

__global__ void reset_kernel() {
    if (threadIdx.x < E) g_cnt[threadIdx.x] = 0;
}

// ---------------------------------------------------------------------------
// fp32 -> fp16 conversion (8 elems per thread, grid-stride-free exact launch)
// ---------------------------------------------------------------------------
__device__ __forceinline__ uint4 pack8(float4 a, float4 b) {
    __half2 h0 = __floats2half2_rn(a.x, a.y);
    __half2 h1 = __floats2half2_rn(a.z, a.w);
    __half2 h2 = __floats2half2_rn(b.x, b.y);
    __half2 h3 = __floats2half2_rn(b.z, b.w);
    uint4 u;
    u.x = *reinterpret_cast<uint32_t*>(&h0);
    u.y = *reinterpret_cast<uint32_t*>(&h1);
    u.z = *reinterpret_cast<uint32_t*>(&h2);
    u.w = *reinterpret_cast<uint32_t*>(&h3);
    return u;
}

__global__ void cvt_kernel(const float* __restrict__ src, __half* __restrict__ dst,
                           int n8 /* n/8 */)
{
    const int i = blockIdx.x * blockDim.x + threadIdx.x;
    if (i >= n8) return;
    const float4 a = reinterpret_cast<const float4*>(src)[2 * i];
    const float4 b = reinterpret_cast<const float4*>(src)[2 * i + 1];
    reinterpret_cast<uint4*>(dst)[i] = pack8(a, b);
}

// ---------------------------------------------------------------------------
// Router: one warp per token, noisy top-2 gating + atomic per-expert
// compaction. Row values are position-invariant -> deterministic output.
// ---------------------------------------------------------------------------
__global__ void router_kernel(const float* __restrict__ x,
                              const float* __restrict__ noise,
                              const float* __restrict__ Wg,
                              const float* __restrict__ bg,
                              const float* __restrict__ Wn,
                              const float* __restrict__ bn)
{
    const int warp = (blockIdx.x * blockDim.x + threadIdx.x) >> 5;
    const int lane = threadIdx.x & 31;
    if (warp >= T) return;

    const float* xr = x + (size_t)warp * D;
    float xv[D / 32];
    #pragma unroll
    for (int i = 0; i < D / 32; i++) xv[i] = xr[lane + 32 * i];

    float nz[E];
    #pragma unroll
    for (int e = 0; e < E; e++) {
        const float* g  = Wg + e * D;
        const float* nw = Wn + e * D;
        float s1 = 0.f, s2 = 0.f;
        #pragma unroll
        for (int i = 0; i < D / 32; i++) {
            const float xi = xv[i];
            s1 = fmaf(xi, g[lane + 32 * i], s1);
            s2 = fmaf(xi, nw[lane + 32 * i], s2);
        }
        #pragma unroll
        for (int off = 16; off; off >>= 1) {
            s1 += __shfl_xor_sync(0xffffffffu, s1, off);
            s2 += __shfl_xor_sync(0xffffffffu, s2, off);
        }
        const float logit = s1 + bg[e];
        const float nlog  = s2 + bn[e];
        const float sp = fmaxf(nlog, 0.f) + log1pf(expf(-fabsf(nlog)));
        nz[e] = logit + noise[warp * E + e] * sp;
    }

    if (lane == 0) {
        int i0 = 0; float v0 = nz[0];
        #pragma unroll
        for (int e = 1; e < E; e++) if (nz[e] > v0) { v0 = nz[e]; i0 = e; }
        int i1 = -1; float v1 = -3.0e38f;
        #pragma unroll
        for (int e = 0; e < E; e++) if (e != i0 && nz[e] > v1) { v1 = nz[e]; i1 = e; }

        const float ex = expf(v1 - v0);
        const float inv = 1.f / (1.f + ex);

        const int p0 = atomicAdd(&g_cnt[i0], 1);
        const int p1 = atomicAdd(&g_cnt[i1], 1);
        const int r0 = i0 * T + p0;
        const int r1 = i1 * T + p1;
        g_tok[r0] = warp;
        g_tok[r1] = warp;
        g_rowof[2 * warp]     = r0;
        g_rowof[2 * warp + 1] = r1;
        g_w[2 * warp]     = inv;
        g_w[2 * warp + 1] = ex * inv;
    }
}

// ---------------------------------------------------------------------------
// helpers
// ---------------------------------------------------------------------------
__device__ __forceinline__ uint32_t smem_u32(const void* p) {
    return (uint32_t)__cvta_generic_to_shared(p);
}
__device__ __forceinline__ void cp16(uint32_t dst, const void* src) {
    asm volatile("cp.async.cg.shared.global [%0], [%1], 16;"
                 :: "r"(dst), "l"(src) : "memory");
}
__device__ __forceinline__ void cp_commit() {
    asm volatile("cp.async.commit_group;" ::: "memory");
}
template <int N>
__device__ __forceinline__ void cp_wait() {
    asm volatile("cp.async.wait_group %0;" :: "n"(N) : "memory");
}
__device__ __forceinline__ void ldsm4(uint32_t& r0, uint32_t& r1, uint32_t& r2, uint32_t& r3,
                                      uint32_t addr) {
    asm volatile("ldmatrix.sync.aligned.m8n8.x4.shared.b16 {%0,%1,%2,%3}, [%4];"
                 : "=r"(r0), "=r"(r1), "=r"(r2), "=r"(r3) : "r"(addr));
}
__device__ __forceinline__ void mma_f16(float& c0, float& c1, float& c2, float& c3,
                                        uint32_t a0, uint32_t a1, uint32_t a2, uint32_t a3,
                                        uint32_t b0, uint32_t b1) {
    asm volatile(
        "mma.sync.aligned.m16n8k16.row.col.f32.f16.f16.f32 "
        "{%0,%1,%2,%3}, {%4,%5,%6,%7}, {%8,%9}, {%0,%1,%2,%3};"
        : "+f"(c0), "+f"(c1), "+f"(c2), "+f"(c3)
        : "r"(a0), "r"(a1), "r"(a2), "r"(a3), "r"(b0), "r"(b1));
}

// ---------------------------------------------------------------------------
// Grouped fp16 tensor-core GEMM, 4-stage cp.async pipeline, all-fp16 operands.
//   MODE 0: H = relu(gather(xh) @ W1h[e]^T + b1);  K=768,  N=3072, out fp16
//   MODE 1: Y = Hh @ W2h[e]^T (+b2 on split 0);    K=1536/split, N=768, out fp32
// ---------------------------------------------------------------------------
template <int MODE>
__global__ __launch_bounds__(256, 2)
void gemm_f16_kernel(const __half* __restrict__ Wh,
                     const float* __restrict__ bias)
{
    constexpr int KROW = (MODE == 0) ? D : DFF;      // row stride of A and W
    constexpr int NTOT = (MODE == 0) ? DFF : D;
    constexpr int KLEN = (MODE == 0) ? D : (DFF / 2);

    int e, sK;
    if (MODE == 0) { e = blockIdx.z; sK = 0; }
    else           { e = blockIdx.z & (E - 1); sK = blockIdx.z >> 3; }
    const int ks0 = (MODE == 1) ? sK * KLEN : 0;

    const int cnt = g_cnt[e];
    const int m0  = blockIdx.y * BM;
    if (m0 >= cnt) return;
    const int n0  = blockIdx.x * BN;

    __shared__ __half As[STAGES][BM][SA];
    __shared__ __half Bs[STAGES][BM][SA];

    const int tid  = threadIdx.x;
    const int lane = tid & 31;
    const int warp = tid >> 5;
    const int wm   = warp >> 2;        // 0..1
    const int wn   = warp & 3;         // 0..3
    const int g    = lane >> 2;
    const int q    = lane & 3;

    // staging mapping: 128 rows x 16 halves, one 16B chunk per thread per operand
    const int lrow = tid >> 1;
    const int cg   = (tid & 1) * 8;

    const __half* Arow;
    {
        const int am = m0 + lrow;
        if (MODE == 0) {
            const int tok = (am < cnt) ? g_tok[e * T + am] : 0;
            Arow = g_xh + (size_t)tok * KROW + cg;
        } else {
            const int r = (am < cnt) ? am : 0;
            Arow = g_Hh + ((size_t)e * T + r) * KROW + ks0 + cg;
        }
    }
    const __half* Brow = Wh + ((size_t)e * NTOT + n0 + lrow) * KROW + ks0 + cg;

    const uint32_t aSt = smem_u32(&As[0][lrow][cg]);
    const uint32_t bSt = smem_u32(&Bs[0][lrow][cg]);

    // ldmatrix lane base addresses (stage 0)
    uint32_t aAddr[4], bAddr[2];
    {
        const int rin = lane & 15;
        const int ch  = lane >> 4;
        #pragma unroll
        for (int mi = 0; mi < 4; mi++)
            aAddr[mi] = smem_u32(&As[0][wm * 64 + mi * 16 + rin][ch * 8]);
    }
    {
        const int rin = ((lane >> 4) << 3) + (lane & 7);
        const int ch  = (lane >> 3) & 1;
        #pragma unroll
        for (int p = 0; p < 2; p++)
            bAddr[p] = smem_u32(&Bs[0][wn * 32 + p * 16 + rin][ch * 8]);
    }

    float acc[4][4][4];
    #pragma unroll
    for (int mi = 0; mi < 4; mi++)
        #pragma unroll
        for (int ni = 0; ni < 4; ni++)
            #pragma unroll
            for (int r = 0; r < 4; r++) acc[mi][ni][r] = 0.f;

    constexpr int NKT = KLEN / BK;

    // prologue: fill stages 0..STAGES-2
    #pragma unroll
    for (int s = 0; s < STAGES - 1; s++) {
        cp16(aSt + s * STG_BYTES, Arow + s * BK);
        cp16(bSt + s * STG_BYTES, Brow + s * BK);
        cp_commit();
    }

    for (int kt = 0; kt < NKT; kt++) {
        cp_wait<STAGES - 2>();
        __syncthreads();

        // issue next stage (into the buffer read last iteration)
        if (kt + STAGES - 1 < NKT) {
            const int nb = (kt + STAGES - 1) & (STAGES - 1);
            const int ko = (kt + STAGES - 1) * BK;
            cp16(aSt + nb * STG_BYTES, Arow + ko);
            cp16(bSt + nb * STG_BYTES, Brow + ko);
        }
        cp_commit();

        const uint32_t off = (uint32_t)((kt & (STAGES - 1)) * STG_BYTES);
        uint32_t af[4][4], bf[4][2];
        #pragma unroll
        for (int mi = 0; mi < 4; mi++)
            ldsm4(af[mi][0], af[mi][1], af[mi][2], af[mi][3], aAddr[mi] + off);
        #pragma unroll
        for (int p = 0; p < 2; p++) {
            uint32_t r0, r1, r2, r3;
            ldsm4(r0, r1, r2, r3, bAddr[p] + off);
            bf[2 * p][0] = r0;     bf[2 * p][1] = r1;
            bf[2 * p + 1][0] = r2; bf[2 * p + 1][1] = r3;
        }
        #pragma unroll
        for (int mi = 0; mi < 4; mi++)
            #pragma unroll
            for (int ni = 0; ni < 4; ni++)
                mma_f16(acc[mi][ni][0], acc[mi][ni][1], acc[mi][ni][2], acc[mi][ni][3],
                        af[mi][0], af[mi][1], af[mi][2], af[mi][3],
                        bf[ni][0], bf[ni][1]);
    }

    // ---- epilogue ----
    const float* be = bias + (size_t)e * NTOT;
    if (MODE == 0) {
        __half* Cb = g_Hh + (size_t)e * T * NTOT;
        #pragma unroll
        for (int mi = 0; mi < 4; mi++) {
            #pragma unroll
            for (int hh = 0; hh < 2; hh++) {
                const int m = m0 + wm * 64 + mi * 16 + g + hh * 8;
                if (m < cnt) {
                    __half* cr = Cb + (size_t)m * NTOT;
                    #pragma unroll
                    for (int ni = 0; ni < 4; ni++) {
                        const int c = n0 + wn * 32 + ni * 8 + 2 * q;
                        float v0 = acc[mi][ni][2 * hh]     + be[c];
                        float v1 = acc[mi][ni][2 * hh + 1] + be[c + 1];
                        v0 = fmaxf(v0, 0.f); v1 = fmaxf(v1, 0.f);
                        *reinterpret_cast<__half2*>(cr + c) = __floats2half2_rn(v0, v1);
                    }
                }
            }
        }
    } else {
        float* Cb = g_Y[sK] + (size_t)e * T * NTOT;
        #pragma unroll
        for (int mi = 0; mi < 4; mi++) {
            #pragma unroll
            for (int hh = 0; hh < 2; hh++) {
                const int m = m0 + wm * 64 + mi * 16 + g + hh * 8;
                if (m < cnt) {
                    float* cr = Cb + (size_t)m * NTOT;
                    #pragma unroll
                    for (int ni = 0; ni < 4; ni++) {
                        const int c = n0 + wn * 32 + ni * 8 + 2 * q;
                        float v0 = acc[mi][ni][2 * hh];
                        float v1 = acc[mi][ni][2 * hh + 1];
                        if (sK == 0) { v0 += be[c]; v1 += be[c + 1]; }
                        *reinterpret_cast<float2*>(cr + c) = make_float2(v0, v1);
                    }
                }
            }
        }
    }
}

// ---------------------------------------------------------------------------
// Combine (deterministic): out[t] = w0*(Y0[r0]+Y1[r0]) + w1*(Y0[r1]+Y1[r1])
// ---------------------------------------------------------------------------
__global__ void combine_kernel(float* __restrict__ out)
{
    const int t = blockIdx.x;
    const int j = threadIdx.x;            // 0..191
    const int r0 = g_rowof[2 * t];
    const int r1 = g_rowof[2 * t + 1];
    const float w0 = g_w[2 * t];
    const float w1 = g_w[2 * t + 1];
    const float4 a0 = reinterpret_cast<const float4*>(g_Y[0] + (size_t)r0 * D)[j];
    const float4 a1 = reinterpret_cast<const float4*>(g_Y[1] + (size_t)r0 * D)[j];
    const float4 b0 = reinterpret_cast<const float4*>(g_Y[0] + (size_t)r1 * D)[j];
    const float4 b1 = reinterpret_cast<const float4*>(g_Y[1] + (size_t)r1 * D)[j];
    float4 o;
    o.x = fmaf(w0, a0.x + a1.x, w1 * (b0.x + b1.x));
    o.y = fmaf(w0, a0.y + a1.y, w1 * (b0.y + b1.y));
    o.z = fmaf(w0, a0.z + a1.z, w1 * (b0.z + b1.z));
    o.w = fmaf(w0, a0.w + a1.w, w1 * (b0.w + b1.w));
    reinterpret_cast<float4*>(out + (size_t)t * D)[j] = o;
}

// ---------------------------------------------------------------------------
// Launch
// ---------------------------------------------------------------------------
extern "C" void kernel_launch(void* const* d_in, const int* in_sizes, int n_in,
                              void* d_out, int out_size)
{
    const float* x     = (const float*)d_in[0];
    const float* noise = (const float*)d_in[1];
    const float* Wg    = (const float*)d_in[2];
    const float* bg    = (const float*)d_in[3];
    const float* Wn    = (const float*)d_in[4];
    const float* bn    = (const float*)d_in[5];
    const float* W1    = (const float*)d_in[6];
    const float* b1    = (const float*)d_in[7];
    const float* W2    = (const float*)d_in[8];
    const float* b2    = (const float*)d_in[9];
    float* out = (float*)d_out;

    reset_kernel<<<1, 32>>>();

    // fp32 -> fp16 conversions (x, W1, W2)
    {
        __half* xh; cudaGetSymbolAddress((void**)&xh, g_xh);
        __half* w1h; cudaGetSymbolAddress((void**)&w1h, g_W1h);
        __half* w2h; cudaGetSymbolAddress((void**)&w2h, g_W2h);
        const int nx = T * D / 8;
        const int nw = E * DFF * D / 8;
        cvt_kernel<<<(nx + 255) / 256, 256>>>(x, xh, nx);
        cvt_kernel<<<(nw + 255) / 256, 256>>>(W1, w1h, nw);
        cvt_kernel<<<(nw + 255) / 256, 256>>>(W2, w2h, nw);
    }

    router_kernel<<<T / 8, 256>>>(x, noise, Wg, bg, Wn, bn);

    // GEMM1: H = relu(xh_gathered @ W1h[e]^T + b1[e])   N=3072, K=768
    {
        __half* w1h; cudaGetSymbolAddress((void**)&w1h, g_W1h);
        dim3 grid(DFF / BN, T / BM, E);
        gemm_f16_kernel<0><<<grid, 256>>>(w1h, b1);
    }
    // GEMM2: Y = Hh @ W2h[e]^T + b2[e], split-K=2       N=768, K=3072
    {
        __half* w2h; cudaGetSymbolAddress((void**)&w2h, g_W2h);
        dim3 grid(D / BN, T / BM, 2 * E);
        gemm_f16_kernel<1><<<grid, 256>>>(w2h, b2);
    }

    combine_kernel<<<T, D / 4>>>(out);
}

// round 6
// speedup vs baseline: 4.3516x; 1.0286x over previous
#include <cuda_runtime.h>
#include <cuda_fp16.h>
#include <math.h>
#include <stdint.h>

// Problem constants: B=2, S=1024 -> T=2048 tokens; D=768; E=8 experts; DFF=3072; top-2.
#define T    2048
#define D    768
#define E    8
#define DFF  3072

// GEMM tiling: 128x256 CTA tile, BK=16, 8 warps (2x4), 64x64 warp tiles,
// fp16 mma.sync m16n8k16 + ldmatrix, 3-stage cp.async pipeline (dynamic smem).
#define BM 128
#define BN 256
#define BK 16
#define SA 24                       // smem row stride (halves): 16 + 8 pad
#define STAGES 3
#define STG_ROWS (BM + BN)          // 384 rows (A then B) per stage
#define STG_BYTES (STG_ROWS * SA * 2)   // 18432 B per stage
#define SMEM_TOT (STAGES * STG_BYTES)   // 55296 B

// ---------------------------------------------------------------------------
// Device scratch
// ---------------------------------------------------------------------------
__device__ int    g_cnt[E];
__device__ int    g_tok[E * T];
__device__ int    g_rowof[T * 2];
__device__ float  g_w[T * 2];
__device__ __half g_xh[T * D];                    // x in fp16
__device__ __half g_W1h[(size_t)E * DFF * D];     // W1 in fp16
__device__ __half g_W2h[(size_t)E * D * DFF];     // W2 in fp16
__device__ __half g_Hh[(size_t)E * T * DFF];      // hidden acts, fp16
__device__ float  g_Y[2][E * T * D];              // split-K partial outputs

__global__ void reset_kernel() {
    if (threadIdx.x < E) g_cnt[threadIdx.x] = 0;
}

// ---------------------------------------------------------------------------
// fp32 -> fp16 conversion for x, W1, W2 in one launch (8 elems / thread)
// ---------------------------------------------------------------------------
__device__ __forceinline__ uint4 pack8(float4 a, float4 b) {
    __half2 h0 = __floats2half2_rn(a.x, a.y);
    __half2 h1 = __floats2half2_rn(a.z, a.w);
    __half2 h2 = __floats2half2_rn(b.x, b.y);
    __half2 h3 = __floats2half2_rn(b.z, b.w);
    uint4 u;
    u.x = *reinterpret_cast<uint32_t*>(&h0);
    u.y = *reinterpret_cast<uint32_t*>(&h1);
    u.z = *reinterpret_cast<uint32_t*>(&h2);
    u.w = *reinterpret_cast<uint32_t*>(&h3);
    return u;
}

__global__ void cvt3_kernel(const float* __restrict__ x,
                            const float* __restrict__ W1,
                            const float* __restrict__ W2,
                            __half* __restrict__ xh,
                            __half* __restrict__ w1h,
                            __half* __restrict__ w2h,
                            int nx8, int nw8)
{
    const int i = blockIdx.x * blockDim.x + threadIdx.x;
    const float* src; __half* dst; int j;
    if (i < nx8)            { src = x;  dst = xh;  j = i; }
    else if (i < nx8 + nw8) { src = W1; dst = w1h; j = i - nx8; }
    else if (i < nx8 + 2 * nw8) { src = W2; dst = w2h; j = i - nx8 - nw8; }
    else return;
    const float4 a = reinterpret_cast<const float4*>(src)[2 * j];
    const float4 b = reinterpret_cast<const float4*>(src)[2 * j + 1];
    reinterpret_cast<uint4*>(dst)[j] = pack8(a, b);
}

// ---------------------------------------------------------------------------
// Router: one warp per token, noisy top-2 gating + atomic per-expert
// compaction. Row values are position-invariant -> deterministic output.
// ---------------------------------------------------------------------------
__global__ void router_kernel(const float* __restrict__ x,
                              const float* __restrict__ noise,
                              const float* __restrict__ Wg,
                              const float* __restrict__ bg,
                              const float* __restrict__ Wn,
                              const float* __restrict__ bn)
{
    const int warp = (blockIdx.x * blockDim.x + threadIdx.x) >> 5;
    const int lane = threadIdx.x & 31;
    if (warp >= T) return;

    const float* xr = x + (size_t)warp * D;
    float xv[D / 32];
    #pragma unroll
    for (int i = 0; i < D / 32; i++) xv[i] = xr[lane + 32 * i];

    float nz[E];
    #pragma unroll
    for (int e = 0; e < E; e++) {
        const float* g  = Wg + e * D;
        const float* nw = Wn + e * D;
        float s1 = 0.f, s2 = 0.f;
        #pragma unroll
        for (int i = 0; i < D / 32; i++) {
            const float xi = xv[i];
            s1 = fmaf(xi, g[lane + 32 * i], s1);
            s2 = fmaf(xi, nw[lane + 32 * i], s2);
        }
        #pragma unroll
        for (int off = 16; off; off >>= 1) {
            s1 += __shfl_xor_sync(0xffffffffu, s1, off);
            s2 += __shfl_xor_sync(0xffffffffu, s2, off);
        }
        const float logit = s1 + bg[e];
        const float nlog  = s2 + bn[e];
        const float sp = fmaxf(nlog, 0.f) + log1pf(expf(-fabsf(nlog)));
        nz[e] = logit + noise[warp * E + e] * sp;
    }

    if (lane == 0) {
        int i0 = 0; float v0 = nz[0];
        #pragma unroll
        for (int e = 1; e < E; e++) if (nz[e] > v0) { v0 = nz[e]; i0 = e; }
        int i1 = -1; float v1 = -3.0e38f;
        #pragma unroll
        for (int e = 0; e < E; e++) if (e != i0 && nz[e] > v1) { v1 = nz[e]; i1 = e; }

        const float ex = expf(v1 - v0);
        const float inv = 1.f / (1.f + ex);

        const int p0 = atomicAdd(&g_cnt[i0], 1);
        const int p1 = atomicAdd(&g_cnt[i1], 1);
        const int r0 = i0 * T + p0;
        const int r1 = i1 * T + p1;
        g_tok[r0] = warp;
        g_tok[r1] = warp;
        g_rowof[2 * warp]     = r0;
        g_rowof[2 * warp + 1] = r1;
        g_w[2 * warp]     = inv;
        g_w[2 * warp + 1] = ex * inv;
    }
}

// ---------------------------------------------------------------------------
// helpers
// ---------------------------------------------------------------------------
__device__ __forceinline__ uint32_t smem_u32(const void* p) {
    return (uint32_t)__cvta_generic_to_shared(p);
}
__device__ __forceinline__ void cp16(uint32_t dst, const void* src) {
    asm volatile("cp.async.cg.shared.global [%0], [%1], 16;"
                 :: "r"(dst), "l"(src) : "memory");
}
__device__ __forceinline__ void cp_commit() {
    asm volatile("cp.async.commit_group;" ::: "memory");
}
template <int N>
__device__ __forceinline__ void cp_wait() {
    asm volatile("cp.async.wait_group %0;" :: "n"(N) : "memory");
}
__device__ __forceinline__ void ldsm4(uint32_t& r0, uint32_t& r1, uint32_t& r2, uint32_t& r3,
                                      uint32_t addr) {
    asm volatile("ldmatrix.sync.aligned.m8n8.x4.shared.b16 {%0,%1,%2,%3}, [%4];"
                 : "=r"(r0), "=r"(r1), "=r"(r2), "=r"(r3) : "r"(addr));
}
__device__ __forceinline__ void mma_f16(float& c0, float& c1, float& c2, float& c3,
                                        uint32_t a0, uint32_t a1, uint32_t a2, uint32_t a3,
                                        uint32_t b0, uint32_t b1) {
    asm volatile(
        "mma.sync.aligned.m16n8k16.row.col.f32.f16.f16.f32 "
        "{%0,%1,%2,%3}, {%4,%5,%6,%7}, {%8,%9}, {%0,%1,%2,%3};"
        : "+f"(c0), "+f"(c1), "+f"(c2), "+f"(c3)
        : "r"(a0), "r"(a1), "r"(a2), "r"(a3), "r"(b0), "r"(b1));
}

// ---------------------------------------------------------------------------
// Grouped fp16 tensor-core GEMM. 128x256 tile, 64x64 warp tiles, 3-stage
// cp.async pipeline, all-fp16 operands.
//   MODE 0: H = relu(gather(xh) @ W1h[e]^T + b1);  K=768,  N=3072, out fp16
//   MODE 1: Y = Hh @ W2h[e]^T (+b2 on split 0);    K=1536/split, N=768, out fp32
// ---------------------------------------------------------------------------
template <int MODE>
__global__ __launch_bounds__(256, 1)
void gemm_f16_kernel(const __half* __restrict__ Wh,
                     const float* __restrict__ bias)
{
    constexpr int KROW = (MODE == 0) ? D : DFF;      // row stride of A and W
    constexpr int NTOT = (MODE == 0) ? DFF : D;
    constexpr int KLEN = (MODE == 0) ? D : (DFF / 2);
    constexpr int NKT  = KLEN / BK;

    extern __shared__ __half sm[];

    int e, sK;
    if (MODE == 0) { e = blockIdx.z; sK = 0; }
    else           { e = blockIdx.z & (E - 1); sK = blockIdx.z >> 3; }
    const int ks0 = (MODE == 1) ? sK * KLEN : 0;

    const int cnt = g_cnt[e];
    const int m0  = blockIdx.y * BM;
    if (m0 >= cnt) return;
    const int n0  = blockIdx.x * BN;

    const int tid  = threadIdx.x;
    const int lane = tid & 31;
    const int warp = tid >> 5;
    const int wm   = warp >> 2;        // 0..1  (64-row slices)
    const int wn   = warp & 3;         // 0..3  (64-col slices)
    const int g    = lane >> 2;
    const int q    = lane & 3;

    // ---- staging: 384 rows x 16 halves; 768 16B-chunks; 3 chunks / thread ----
    const __half* src[3];
    uint32_t      stA[3];
    const uint32_t smb = smem_u32(sm);
    #pragma unroll
    for (int k = 0; k < 3; k++) {
        const int c   = tid + 256 * k;
        const int rc  = c >> 1;
        const int cc8 = (c & 1) * 8;
        stA[k] = smb + (uint32_t)(rc * SA + cc8) * 2;
        if (rc < BM) {
            const int am = m0 + rc;
            if (MODE == 0) {
                const int tok = (am < cnt) ? g_tok[e * T + am] : 0;
                src[k] = g_xh + (size_t)tok * KROW + cc8;
            } else {
                const int r = (am < cnt) ? am : 0;
                src[k] = g_Hh + ((size_t)e * T + r) * KROW + ks0 + cc8;
            }
        } else {
            src[k] = Wh + ((size_t)e * NTOT + n0 + (rc - BM)) * KROW + ks0 + cc8;
        }
    }

    // ---- ldmatrix lane base addresses (stage 0) ----
    uint32_t aAddr[4], bAddr[4];
    {
        const int rin = lane & 15;
        const int ch  = lane >> 4;
        #pragma unroll
        for (int mi = 0; mi < 4; mi++)
            aAddr[mi] = smb + (uint32_t)((wm * 64 + mi * 16 + rin) * SA + ch * 8) * 2;
    }
    {
        const int rin = ((lane >> 4) << 3) + (lane & 7);
        const int ch  = (lane >> 3) & 1;
        #pragma unroll
        for (int p = 0; p < 4; p++)
            bAddr[p] = smb + (uint32_t)((BM + wn * 64 + p * 16 + rin) * SA + ch * 8) * 2;
    }

    float acc[4][8][4];
    #pragma unroll
    for (int mi = 0; mi < 4; mi++)
        #pragma unroll
        for (int ni = 0; ni < 8; ni++)
            #pragma unroll
            for (int r = 0; r < 4; r++) acc[mi][ni][r] = 0.f;

    // prologue: fill stages 0..1
    #pragma unroll
    for (int s = 0; s < STAGES - 1; s++) {
        #pragma unroll
        for (int k = 0; k < 3; k++)
            cp16(stA[k] + s * STG_BYTES, src[k] + s * BK);
        cp_commit();
    }

    int cur = 0;
    for (int kt = 0; kt < NKT; kt++) {
        cp_wait<STAGES - 2>();
        __syncthreads();

        // issue next stage into the buffer freed last iteration
        if (kt + STAGES - 1 < NKT) {
            int tgt = cur + 2; if (tgt >= STAGES) tgt -= STAGES;
            const int ko = (kt + STAGES - 1) * BK;
            #pragma unroll
            for (int k = 0; k < 3; k++)
                cp16(stA[k] + tgt * STG_BYTES, src[k] + ko);
        }
        cp_commit();

        const uint32_t off = (uint32_t)(cur * STG_BYTES);
        uint32_t af[4][4], bf[8][2];
        #pragma unroll
        for (int mi = 0; mi < 4; mi++)
            ldsm4(af[mi][0], af[mi][1], af[mi][2], af[mi][3], aAddr[mi] + off);
        #pragma unroll
        for (int p = 0; p < 4; p++) {
            uint32_t r0, r1, r2, r3;
            ldsm4(r0, r1, r2, r3, bAddr[p] + off);
            bf[2 * p][0] = r0;     bf[2 * p][1] = r1;
            bf[2 * p + 1][0] = r2; bf[2 * p + 1][1] = r3;
        }
        #pragma unroll
        for (int mi = 0; mi < 4; mi++)
            #pragma unroll
            for (int ni = 0; ni < 8; ni++)
                mma_f16(acc[mi][ni][0], acc[mi][ni][1], acc[mi][ni][2], acc[mi][ni][3],
                        af[mi][0], af[mi][1], af[mi][2], af[mi][3],
                        bf[ni][0], bf[ni][1]);

        cur = cur + 1; if (cur >= STAGES) cur = 0;
    }

    // ---- epilogue ----
    const float* be = bias + (size_t)e * NTOT;
    if (MODE == 0) {
        __half* Cb = g_Hh + (size_t)e * T * NTOT;
        #pragma unroll
        for (int mi = 0; mi < 4; mi++) {
            #pragma unroll
            for (int hh = 0; hh < 2; hh++) {
                const int m = m0 + wm * 64 + mi * 16 + g + hh * 8;
                if (m < cnt) {
                    __half* cr = Cb + (size_t)m * NTOT;
                    #pragma unroll
                    for (int ni = 0; ni < 8; ni++) {
                        const int c = n0 + wn * 64 + ni * 8 + 2 * q;
                        float v0 = acc[mi][ni][2 * hh]     + be[c];
                        float v1 = acc[mi][ni][2 * hh + 1] + be[c + 1];
                        v0 = fmaxf(v0, 0.f); v1 = fmaxf(v1, 0.f);
                        *reinterpret_cast<__half2*>(cr + c) = __floats2half2_rn(v0, v1);
                    }
                }
            }
        }
    } else {
        float* Cb = g_Y[sK] + (size_t)e * T * NTOT;
        #pragma unroll
        for (int mi = 0; mi < 4; mi++) {
            #pragma unroll
            for (int hh = 0; hh < 2; hh++) {
                const int m = m0 + wm * 64 + mi * 16 + g + hh * 8;
                if (m < cnt) {
                    float* cr = Cb + (size_t)m * NTOT;
                    #pragma unroll
                    for (int ni = 0; ni < 8; ni++) {
                        const int c = n0 + wn * 64 + ni * 8 + 2 * q;
                        float v0 = acc[mi][ni][2 * hh];
                        float v1 = acc[mi][ni][2 * hh + 1];
                        if (sK == 0) { v0 += be[c]; v1 += be[c + 1]; }
                        *reinterpret_cast<float2*>(cr + c) = make_float2(v0, v1);
                    }
                }
            }
        }
    }
}

// ---------------------------------------------------------------------------
// Combine (deterministic): out[t] = w0*(Y0[r0]+Y1[r0]) + w1*(Y0[r1]+Y1[r1])
// ---------------------------------------------------------------------------
__global__ void combine_kernel(float* __restrict__ out)
{
    const int t = blockIdx.x;
    const int j = threadIdx.x;            // 0..191
    const int r0 = g_rowof[2 * t];
    const int r1 = g_rowof[2 * t + 1];
    const float w0 = g_w[2 * t];
    const float w1 = g_w[2 * t + 1];
    const float4 a0 = reinterpret_cast<const float4*>(g_Y[0] + (size_t)r0 * D)[j];
    const float4 a1 = reinterpret_cast<const float4*>(g_Y[1] + (size_t)r0 * D)[j];
    const float4 b0 = reinterpret_cast<const float4*>(g_Y[0] + (size_t)r1 * D)[j];
    const float4 b1 = reinterpret_cast<const float4*>(g_Y[1] + (size_t)r1 * D)[j];
    float4 o;
    o.x = fmaf(w0, a0.x + a1.x, w1 * (b0.x + b1.x));
    o.y = fmaf(w0, a0.y + a1.y, w1 * (b0.y + b1.y));
    o.z = fmaf(w0, a0.z + a1.z, w1 * (b0.z + b1.z));
    o.w = fmaf(w0, a0.w + a1.w, w1 * (b0.w + b1.w));
    reinterpret_cast<float4*>(out + (size_t)t * D)[j] = o;
}

// ---------------------------------------------------------------------------
// Launch
// ---------------------------------------------------------------------------
extern "C" void kernel_launch(void* const* d_in, const int* in_sizes, int n_in,
                              void* d_out, int out_size)
{
    const float* x     = (const float*)d_in[0];
    const float* noise = (const float*)d_in[1];
    const float* Wg    = (const float*)d_in[2];
    const float* bg    = (const float*)d_in[3];
    const float* Wn    = (const float*)d_in[4];
    const float* bn    = (const float*)d_in[5];
    const float* W1    = (const float*)d_in[6];
    const float* b1    = (const float*)d_in[7];
    const float* W2    = (const float*)d_in[8];
    const float* b2    = (const float*)d_in[9];
    float* out = (float*)d_out;

    cudaFuncSetAttribute(gemm_f16_kernel<0>,
                         cudaFuncAttributeMaxDynamicSharedMemorySize, SMEM_TOT);
    cudaFuncSetAttribute(gemm_f16_kernel<1>,
                         cudaFuncAttributeMaxDynamicSharedMemorySize, SMEM_TOT);

    reset_kernel<<<1, 32>>>();

    // fp32 -> fp16 conversions (x, W1, W2) in one launch
    {
        __half* xh;  cudaGetSymbolAddress((void**)&xh,  g_xh);
        __half* w1h; cudaGetSymbolAddress((void**)&w1h, g_W1h);
        __half* w2h; cudaGetSymbolAddress((void**)&w2h, g_W2h);
        const int nx8 = T * D / 8;
        const int nw8 = E * DFF * D / 8;
        const int tot = nx8 + 2 * nw8;
        cvt3_kernel<<<(tot + 255) / 256, 256>>>(x, W1, W2, xh, w1h, w2h, nx8, nw8);
    }

    router_kernel<<<T / 8, 256>>>(x, noise, Wg, bg, Wn, bn);

    // GEMM1: H = relu(xh_gathered @ W1h[e]^T + b1[e])   N=3072, K=768
    {
        __half* w1h; cudaGetSymbolAddress((void**)&w1h, g_W1h);
        dim3 grid(DFF / BN, T / BM, E);
        gemm_f16_kernel<0><<<grid, 256, SMEM_TOT>>>(w1h, b1);
    }
    // GEMM2: Y = Hh @ W2h[e]^T + b2[e], split-K=2       N=768, K=3072
    {
        __half* w2h; cudaGetSymbolAddress((void**)&w2h, g_W2h);
        dim3 grid(D / BN, T / BM, 2 * E);
        gemm_f16_kernel<1><<<grid, 256, SMEM_TOT>>>(w2h, b2);
    }

    combine_kernel<<<T, D / 4>>>(out);
}

// round 7
// speedup vs baseline: 4.6932x; 1.0785x over previous
#include <cuda_runtime.h>
#include <cuda_fp16.h>
#include <math.h>
#include <stdint.h>

// Problem constants: B=2, S=1024 -> T=2048 tokens; D=768; E=8 experts; DFF=3072; top-2.
#define T    2048
#define D    768
#define E    8
#define DFF  3072

// GEMM tiling: 128x256 CTA tile, BK=32 (2 x k16 per sync), 8 warps (2x4),
// 64x64 warp tiles, fp16 mma.sync m16n8k16 + ldmatrix, 3-stage cp.async.
#define BM 128
#define BN 256
#define BK 32
#define SA 40                       // smem row stride (halves): 32 + 8 pad
#define STAGES 3
#define STG_ROWS (BM + BN)          // 384 rows (A then B) per stage
#define STG_BYTES (STG_ROWS * SA * 2)   // 30720 B per stage
#define SMEM_TOT (STAGES * STG_BYTES)   // 92160 B
#define SPLITK 4

// ---------------------------------------------------------------------------
// Device scratch
// ---------------------------------------------------------------------------
__device__ int    g_cnt[E];
__device__ int    g_tok[E * T];
__device__ int    g_rowof[T * 2];
__device__ float  g_w[T * 2];
__device__ __half g_xh[T * D];                    // x in fp16
__device__ __half g_W1h[(size_t)E * DFF * D];     // W1 in fp16
__device__ __half g_W2h[(size_t)E * D * DFF];     // W2 in fp16
__device__ __half g_Hh[(size_t)E * T * DFF];      // hidden acts, fp16
__device__ float  g_Y[SPLITK][E * T * D];         // split-K partial outputs

__global__ void reset_kernel() {
    if (threadIdx.x < E) g_cnt[threadIdx.x] = 0;
}

// ---------------------------------------------------------------------------
// fp32 -> fp16 conversion for x, W1, W2 in one launch (8 elems / thread)
// ---------------------------------------------------------------------------
__device__ __forceinline__ uint4 pack8(float4 a, float4 b) {
    __half2 h0 = __floats2half2_rn(a.x, a.y);
    __half2 h1 = __floats2half2_rn(a.z, a.w);
    __half2 h2 = __floats2half2_rn(b.x, b.y);
    __half2 h3 = __floats2half2_rn(b.z, b.w);
    uint4 u;
    u.x = *reinterpret_cast<uint32_t*>(&h0);
    u.y = *reinterpret_cast<uint32_t*>(&h1);
    u.z = *reinterpret_cast<uint32_t*>(&h2);
    u.w = *reinterpret_cast<uint32_t*>(&h3);
    return u;
}

__global__ void cvt3_kernel(const float* __restrict__ x,
                            const float* __restrict__ W1,
                            const float* __restrict__ W2,
                            __half* __restrict__ xh,
                            __half* __restrict__ w1h,
                            __half* __restrict__ w2h,
                            int nx8, int nw8)
{
    const int i = blockIdx.x * blockDim.x + threadIdx.x;
    const float* src; __half* dst; int j;
    if (i < nx8)            { src = x;  dst = xh;  j = i; }
    else if (i < nx8 + nw8) { src = W1; dst = w1h; j = i - nx8; }
    else if (i < nx8 + 2 * nw8) { src = W2; dst = w2h; j = i - nx8 - nw8; }
    else return;
    const float4 a = reinterpret_cast<const float4*>(src)[2 * j];
    const float4 b = reinterpret_cast<const float4*>(src)[2 * j + 1];
    reinterpret_cast<uint4*>(dst)[j] = pack8(a, b);
}

// ---------------------------------------------------------------------------
// Router: one warp per token, noisy top-2 gating + atomic per-expert
// compaction. Row values are position-invariant -> deterministic output.
// ---------------------------------------------------------------------------
__global__ void router_kernel(const float* __restrict__ x,
                              const float* __restrict__ noise,
                              const float* __restrict__ Wg,
                              const float* __restrict__ bg,
                              const float* __restrict__ Wn,
                              const float* __restrict__ bn)
{
    const int warp = (blockIdx.x * blockDim.x + threadIdx.x) >> 5;
    const int lane = threadIdx.x & 31;
    if (warp >= T) return;

    const float* xr = x + (size_t)warp * D;
    float xv[D / 32];
    #pragma unroll
    for (int i = 0; i < D / 32; i++) xv[i] = xr[lane + 32 * i];

    float nz[E];
    #pragma unroll
    for (int e = 0; e < E; e++) {
        const float* g  = Wg + e * D;
        const float* nw = Wn + e * D;
        float s1 = 0.f, s2 = 0.f;
        #pragma unroll
        for (int i = 0; i < D / 32; i++) {
            const float xi = xv[i];
            s1 = fmaf(xi, g[lane + 32 * i], s1);
            s2 = fmaf(xi, nw[lane + 32 * i], s2);
        }
        #pragma unroll
        for (int off = 16; off; off >>= 1) {
            s1 += __shfl_xor_sync(0xffffffffu, s1, off);
            s2 += __shfl_xor_sync(0xffffffffu, s2, off);
        }
        const float logit = s1 + bg[e];
        const float nlog  = s2 + bn[e];
        const float sp = fmaxf(nlog, 0.f) + log1pf(expf(-fabsf(nlog)));
        nz[e] = logit + noise[warp * E + e] * sp;
    }

    if (lane == 0) {
        int i0 = 0; float v0 = nz[0];
        #pragma unroll
        for (int e = 1; e < E; e++) if (nz[e] > v0) { v0 = nz[e]; i0 = e; }
        int i1 = -1; float v1 = -3.0e38f;
        #pragma unroll
        for (int e = 0; e < E; e++) if (e != i0 && nz[e] > v1) { v1 = nz[e]; i1 = e; }

        const float ex = expf(v1 - v0);
        const float inv = 1.f / (1.f + ex);

        const int p0 = atomicAdd(&g_cnt[i0], 1);
        const int p1 = atomicAdd(&g_cnt[i1], 1);
        const int r0 = i0 * T + p0;
        const int r1 = i1 * T + p1;
        g_tok[r0] = warp;
        g_tok[r1] = warp;
        g_rowof[2 * warp]     = r0;
        g_rowof[2 * warp + 1] = r1;
        g_w[2 * warp]     = inv;
        g_w[2 * warp + 1] = ex * inv;
    }
}

// ---------------------------------------------------------------------------
// helpers
// ---------------------------------------------------------------------------
__device__ __forceinline__ uint32_t smem_u32(const void* p) {
    return (uint32_t)__cvta_generic_to_shared(p);
}
__device__ __forceinline__ void cp16(uint32_t dst, const void* src) {
    asm volatile("cp.async.cg.shared.global [%0], [%1], 16;"
                 :: "r"(dst), "l"(src) : "memory");
}
__device__ __forceinline__ void cp_commit() {
    asm volatile("cp.async.commit_group;" ::: "memory");
}
template <int N>
__device__ __forceinline__ void cp_wait() {
    asm volatile("cp.async.wait_group %0;" :: "n"(N) : "memory");
}
__device__ __forceinline__ void ldsm4(uint32_t& r0, uint32_t& r1, uint32_t& r2, uint32_t& r3,
                                      uint32_t addr) {
    asm volatile("ldmatrix.sync.aligned.m8n8.x4.shared.b16 {%0,%1,%2,%3}, [%4];"
                 : "=r"(r0), "=r"(r1), "=r"(r2), "=r"(r3) : "r"(addr));
}
__device__ __forceinline__ void mma_f16(float& c0, float& c1, float& c2, float& c3,
                                        uint32_t a0, uint32_t a1, uint32_t a2, uint32_t a3,
                                        uint32_t b0, uint32_t b1) {
    asm volatile(
        "mma.sync.aligned.m16n8k16.row.col.f32.f16.f16.f32 "
        "{%0,%1,%2,%3}, {%4,%5,%6,%7}, {%8,%9}, {%0,%1,%2,%3};"
        : "+f"(c0), "+f"(c1), "+f"(c2), "+f"(c3)
        : "r"(a0), "r"(a1), "r"(a2), "r"(a3), "r"(b0), "r"(b1));
}

// ---------------------------------------------------------------------------
// Grouped fp16 tensor-core GEMM. 128x256 tile, 64x64 warp tiles, BK=32
// (two k16 sub-steps per sync), 3-stage cp.async pipeline.
//   MODE 0: H = relu(gather(xh) @ W1h[e]^T + b1);   K=768,  N=3072, out fp16
//   MODE 1: Y = Hh @ W2h[e]^T (+b2 on split 0);     K=768/split x4, N=768, fp32
// ---------------------------------------------------------------------------
template <int MODE>
__global__ __launch_bounds__(256, 1)
void gemm_f16_kernel(const __half* __restrict__ Wh,
                     const float* __restrict__ bias)
{
    constexpr int KROW = (MODE == 0) ? D : DFF;      // row stride of A and W
    constexpr int NTOT = (MODE == 0) ? DFF : D;
    constexpr int KLEN = (MODE == 0) ? D : (DFF / SPLITK);
    constexpr int NKT  = KLEN / BK;

    extern __shared__ __half sm[];

    int e, sK;
    if (MODE == 0) { e = blockIdx.z; sK = 0; }
    else           { e = blockIdx.z & (E - 1); sK = blockIdx.z >> 3; }
    const int ks0 = (MODE == 1) ? sK * KLEN : 0;

    const int cnt = g_cnt[e];
    const int m0  = blockIdx.y * BM;
    if (m0 >= cnt) return;
    const int n0  = blockIdx.x * BN;

    const int tid  = threadIdx.x;
    const int lane = tid & 31;
    const int warp = tid >> 5;
    const int wm   = warp >> 2;        // 0..1  (64-row slices)
    const int wn   = warp & 3;         // 0..3  (64-col slices)
    const int g    = lane >> 2;
    const int q    = lane & 3;

    // ---- staging: 384 rows x 32 halves; 1536 16B-chunks; 6 per thread ----
    const __half* src[6];
    uint32_t      stA[6];
    const uint32_t smb = smem_u32(sm);
    #pragma unroll
    for (int k = 0; k < 6; k++) {
        const int c   = tid + 256 * k;
        const int rc  = c >> 2;
        const int cc8 = (c & 3) * 8;
        stA[k] = smb + (uint32_t)(rc * SA + cc8) * 2;
        if (rc < BM) {
            const int am = m0 + rc;
            if (MODE == 0) {
                const int tok = (am < cnt) ? g_tok[e * T + am] : 0;
                src[k] = g_xh + (size_t)tok * KROW + cc8;
            } else {
                const int r = (am < cnt) ? am : 0;
                src[k] = g_Hh + ((size_t)e * T + r) * KROW + ks0 + cc8;
            }
        } else {
            src[k] = Wh + ((size_t)e * NTOT + n0 + (rc - BM)) * KROW + ks0 + cc8;
        }
    }

    // ---- ldmatrix lane base addresses (stage 0, sub-k 0) ----
    uint32_t aAddr[4], bAddr[4];
    {
        const int rin = lane & 15;
        const int ch  = lane >> 4;
        #pragma unroll
        for (int mi = 0; mi < 4; mi++)
            aAddr[mi] = smb + (uint32_t)((wm * 64 + mi * 16 + rin) * SA + ch * 8) * 2;
    }
    {
        const int rin = ((lane >> 4) << 3) + (lane & 7);
        const int ch  = (lane >> 3) & 1;
        #pragma unroll
        for (int p = 0; p < 4; p++)
            bAddr[p] = smb + (uint32_t)((BM + wn * 64 + p * 16 + rin) * SA + ch * 8) * 2;
    }

    float acc[4][8][4];
    #pragma unroll
    for (int mi = 0; mi < 4; mi++)
        #pragma unroll
        for (int ni = 0; ni < 8; ni++)
            #pragma unroll
            for (int r = 0; r < 4; r++) acc[mi][ni][r] = 0.f;

    // prologue: fill stages 0..1
    #pragma unroll
    for (int s = 0; s < STAGES - 1; s++) {
        #pragma unroll
        for (int k = 0; k < 6; k++)
            cp16(stA[k] + s * STG_BYTES, src[k] + s * BK);
        cp_commit();
    }

    int cur = 0;
    for (int kt = 0; kt < NKT; kt++) {
        cp_wait<STAGES - 2>();
        __syncthreads();

        // issue next stage into the buffer freed last iteration
        if (kt + STAGES - 1 < NKT) {
            int tgt = cur + 2; if (tgt >= STAGES) tgt -= STAGES;
            const int ko = (kt + STAGES - 1) * BK;
            #pragma unroll
            for (int k = 0; k < 6; k++)
                cp16(stA[k] + tgt * STG_BYTES, src[k] + ko);
        }
        cp_commit();

        const uint32_t soff = (uint32_t)(cur * STG_BYTES);
        #pragma unroll
        for (int sub = 0; sub < 2; sub++) {
            const uint32_t off = soff + sub * 32;   // +16 halves
            uint32_t af[4][4], bf[8][2];
            #pragma unroll
            for (int mi = 0; mi < 4; mi++)
                ldsm4(af[mi][0], af[mi][1], af[mi][2], af[mi][3], aAddr[mi] + off);
            #pragma unroll
            for (int p = 0; p < 4; p++) {
                uint32_t r0, r1, r2, r3;
                ldsm4(r0, r1, r2, r3, bAddr[p] + off);
                bf[2 * p][0] = r0;     bf[2 * p][1] = r1;
                bf[2 * p + 1][0] = r2; bf[2 * p + 1][1] = r3;
            }
            #pragma unroll
            for (int mi = 0; mi < 4; mi++)
                #pragma unroll
                for (int ni = 0; ni < 8; ni++)
                    mma_f16(acc[mi][ni][0], acc[mi][ni][1], acc[mi][ni][2], acc[mi][ni][3],
                            af[mi][0], af[mi][1], af[mi][2], af[mi][3],
                            bf[ni][0], bf[ni][1]);
        }

        cur = cur + 1; if (cur >= STAGES) cur = 0;
    }

    // ---- epilogue ----
    const float* be = bias + (size_t)e * NTOT;
    if (MODE == 0) {
        __half* Cb = g_Hh + (size_t)e * T * NTOT;
        #pragma unroll
        for (int mi = 0; mi < 4; mi++) {
            #pragma unroll
            for (int hh = 0; hh < 2; hh++) {
                const int m = m0 + wm * 64 + mi * 16 + g + hh * 8;
                if (m < cnt) {
                    __half* cr = Cb + (size_t)m * NTOT;
                    #pragma unroll
                    for (int ni = 0; ni < 8; ni++) {
                        const int c = n0 + wn * 64 + ni * 8 + 2 * q;
                        float v0 = acc[mi][ni][2 * hh]     + be[c];
                        float v1 = acc[mi][ni][2 * hh + 1] + be[c + 1];
                        v0 = fmaxf(v0, 0.f); v1 = fmaxf(v1, 0.f);
                        *reinterpret_cast<__half2*>(cr + c) = __floats2half2_rn(v0, v1);
                    }
                }
            }
        }
    } else {
        float* Cb = g_Y[sK] + (size_t)e * T * NTOT;
        #pragma unroll
        for (int mi = 0; mi < 4; mi++) {
            #pragma unroll
            for (int hh = 0; hh < 2; hh++) {
                const int m = m0 + wm * 64 + mi * 16 + g + hh * 8;
                if (m < cnt) {
                    float* cr = Cb + (size_t)m * NTOT;
                    #pragma unroll
                    for (int ni = 0; ni < 8; ni++) {
                        const int c = n0 + wn * 64 + ni * 8 + 2 * q;
                        float v0 = acc[mi][ni][2 * hh];
                        float v1 = acc[mi][ni][2 * hh + 1];
                        if (sK == 0) { v0 += be[c]; v1 += be[c + 1]; }
                        *reinterpret_cast<float2*>(cr + c) = make_float2(v0, v1);
                    }
                }
            }
        }
    }
}

// ---------------------------------------------------------------------------
// Combine (deterministic): out[t] = w0*sum_s Ys[r0] + w1*sum_s Ys[r1]
// ---------------------------------------------------------------------------
__global__ void combine_kernel(float* __restrict__ out)
{
    const int t = blockIdx.x;
    const int j = threadIdx.x;            // 0..191
    const int r0 = g_rowof[2 * t];
    const int r1 = g_rowof[2 * t + 1];
    const float w0 = g_w[2 * t];
    const float w1 = g_w[2 * t + 1];
    float4 sa = make_float4(0.f, 0.f, 0.f, 0.f);
    float4 sb = make_float4(0.f, 0.f, 0.f, 0.f);
    #pragma unroll
    for (int s = 0; s < SPLITK; s++) {
        const float4 a = reinterpret_cast<const float4*>(g_Y[s] + (size_t)r0 * D)[j];
        const float4 b = reinterpret_cast<const float4*>(g_Y[s] + (size_t)r1 * D)[j];
        sa.x += a.x; sa.y += a.y; sa.z += a.z; sa.w += a.w;
        sb.x += b.x; sb.y += b.y; sb.z += b.z; sb.w += b.w;
    }
    float4 o;
    o.x = fmaf(w0, sa.x, w1 * sb.x);
    o.y = fmaf(w0, sa.y, w1 * sb.y);
    o.z = fmaf(w0, sa.z, w1 * sb.z);
    o.w = fmaf(w0, sa.w, w1 * sb.w);
    reinterpret_cast<float4*>(out + (size_t)t * D)[j] = o;
}

// ---------------------------------------------------------------------------
// Launch
// ---------------------------------------------------------------------------
extern "C" void kernel_launch(void* const* d_in, const int* in_sizes, int n_in,
                              void* d_out, int out_size)
{
    const float* x     = (const float*)d_in[0];
    const float* noise = (const float*)d_in[1];
    const float* Wg    = (const float*)d_in[2];
    const float* bg    = (const float*)d_in[3];
    const float* Wn    = (const float*)d_in[4];
    const float* bn    = (const float*)d_in[5];
    const float* W1    = (const float*)d_in[6];
    const float* b1    = (const float*)d_in[7];
    const float* W2    = (const float*)d_in[8];
    const float* b2    = (const float*)d_in[9];
    float* out = (float*)d_out;

    cudaFuncSetAttribute(gemm_f16_kernel<0>,
                         cudaFuncAttributeMaxDynamicSharedMemorySize, SMEM_TOT);
    cudaFuncSetAttribute(gemm_f16_kernel<1>,
                         cudaFuncAttributeMaxDynamicSharedMemorySize, SMEM_TOT);

    reset_kernel<<<1, 32>>>();

    // fp32 -> fp16 conversions (x, W1, W2) in one launch
    {
        __half* xh;  cudaGetSymbolAddress((void**)&xh,  g_xh);
        __half* w1h; cudaGetSymbolAddress((void**)&w1h, g_W1h);
        __half* w2h; cudaGetSymbolAddress((void**)&w2h, g_W2h);
        const int nx8 = T * D / 8;
        const int nw8 = E * DFF * D / 8;
        const int tot = nx8 + 2 * nw8;
        cvt3_kernel<<<(tot + 255) / 256, 256>>>(x, W1, W2, xh, w1h, w2h, nx8, nw8);
    }

    router_kernel<<<T / 8, 256>>>(x, noise, Wg, bg, Wn, bn);

    // GEMM1: H = relu(xh_gathered @ W1h[e]^T + b1[e])   N=3072, K=768
    {
        __half* w1h; cudaGetSymbolAddress((void**)&w1h, g_W1h);
        dim3 grid(DFF / BN, T / BM, E);
        gemm_f16_kernel<0><<<grid, 256, SMEM_TOT>>>(w1h, b1);
    }
    // GEMM2: Y = Hh @ W2h[e]^T + b2[e], split-K=4       N=768, K=3072
    {
        __half* w2h; cudaGetSymbolAddress((void**)&w2h, g_W2h);
        dim3 grid(D / BN, T / BM, SPLITK * E);
        gemm_f16_kernel<1><<<grid, 256, SMEM_TOT>>>(w2h, b2);
    }

    combine_kernel<<<T, D / 4>>>(out);
}

// round 8
// speedup vs baseline: 5.5339x; 1.1791x over previous
#include <cuda_runtime.h>
#include <cuda_fp16.h>
#include <math.h>
#include <stdint.h>

// Problem constants: B=2, S=1024 -> T=2048 tokens; D=768; E=8 experts; DFF=3072; top-2.
#define T    2048
#define D    768
#define E    8
#define DFF  3072

// GEMM tiling: 128x256 CTA tile, BK=32 (2 x k16 sub-steps), 8 warps (2x4),
// 64x64 warp tiles, fp16 mma.sync m16n8k16 + ldmatrix, 3-stage cp.async,
// software-pipelined fragment double-buffering.
#define BM 128
#define BN 256
#define BK 32
#define SA 40                       // smem row stride (halves): 32 + 8 pad
#define STAGES 3
#define STG_ROWS (BM + BN)          // 384 rows (A then B) per stage
#define STG_BYTES (STG_ROWS * SA * 2)   // 30720 B per stage
#define SMEM_TOT (STAGES * STG_BYTES)   // 92160 B
#define SPLITK 4

// ---------------------------------------------------------------------------
// Device scratch
// ---------------------------------------------------------------------------
__device__ int    g_cnt[E];
__device__ int    g_tok[E * T];
__device__ int    g_rowof[T * 2];
__device__ float  g_w[T * 2];
__device__ __half g_xh[T * D];                    // x in fp16
__device__ __half g_W1h[(size_t)E * DFF * D];     // W1 in fp16
__device__ __half g_W2h[(size_t)E * D * DFF];     // W2 in fp16
__device__ __half g_Hh[(size_t)E * T * DFF];      // hidden acts, fp16
__device__ float  g_Y[SPLITK][E * T * D];         // split-K partial outputs

__global__ void reset_kernel() {
    if (threadIdx.x < E) g_cnt[threadIdx.x] = 0;
}

// ---------------------------------------------------------------------------
// fp32 -> fp16 conversion for x, W1, W2 in one launch (8 elems / thread)
// ---------------------------------------------------------------------------
__device__ __forceinline__ uint4 pack8(float4 a, float4 b) {
    __half2 h0 = __floats2half2_rn(a.x, a.y);
    __half2 h1 = __floats2half2_rn(a.z, a.w);
    __half2 h2 = __floats2half2_rn(b.x, b.y);
    __half2 h3 = __floats2half2_rn(b.z, b.w);
    uint4 u;
    u.x = *reinterpret_cast<uint32_t*>(&h0);
    u.y = *reinterpret_cast<uint32_t*>(&h1);
    u.z = *reinterpret_cast<uint32_t*>(&h2);
    u.w = *reinterpret_cast<uint32_t*>(&h3);
    return u;
}

__global__ void cvt3_kernel(const float* __restrict__ x,
                            const float* __restrict__ W1,
                            const float* __restrict__ W2,
                            __half* __restrict__ xh,
                            __half* __restrict__ w1h,
                            __half* __restrict__ w2h,
                            int nx8, int nw8)
{
    const int i = blockIdx.x * blockDim.x + threadIdx.x;
    const float* src; __half* dst; int j;
    if (i < nx8)            { src = x;  dst = xh;  j = i; }
    else if (i < nx8 + nw8) { src = W1; dst = w1h; j = i - nx8; }
    else if (i < nx8 + 2 * nw8) { src = W2; dst = w2h; j = i - nx8 - nw8; }
    else return;
    const float4 a = reinterpret_cast<const float4*>(src)[2 * j];
    const float4 b = reinterpret_cast<const float4*>(src)[2 * j + 1];
    reinterpret_cast<uint4*>(dst)[j] = pack8(a, b);
}

// ---------------------------------------------------------------------------
// Router: one warp per token, noisy top-2 gating + atomic per-expert
// compaction. Row values are position-invariant -> deterministic output.
// ---------------------------------------------------------------------------
__global__ void router_kernel(const float* __restrict__ x,
                              const float* __restrict__ noise,
                              const float* __restrict__ Wg,
                              const float* __restrict__ bg,
                              const float* __restrict__ Wn,
                              const float* __restrict__ bn)
{
    const int warp = (blockIdx.x * blockDim.x + threadIdx.x) >> 5;
    const int lane = threadIdx.x & 31;
    if (warp >= T) return;

    const float* xr = x + (size_t)warp * D;
    float xv[D / 32];
    #pragma unroll
    for (int i = 0; i < D / 32; i++) xv[i] = xr[lane + 32 * i];

    float nz[E];
    #pragma unroll
    for (int e = 0; e < E; e++) {
        const float* g  = Wg + e * D;
        const float* nw = Wn + e * D;
        float s1 = 0.f, s2 = 0.f;
        #pragma unroll
        for (int i = 0; i < D / 32; i++) {
            const float xi = xv[i];
            s1 = fmaf(xi, g[lane + 32 * i], s1);
            s2 = fmaf(xi, nw[lane + 32 * i], s2);
        }
        #pragma unroll
        for (int off = 16; off; off >>= 1) {
            s1 += __shfl_xor_sync(0xffffffffu, s1, off);
            s2 += __shfl_xor_sync(0xffffffffu, s2, off);
        }
        const float logit = s1 + bg[e];
        const float nlog  = s2 + bn[e];
        const float sp = fmaxf(nlog, 0.f) + log1pf(expf(-fabsf(nlog)));
        nz[e] = logit + noise[warp * E + e] * sp;
    }

    if (lane == 0) {
        int i0 = 0; float v0 = nz[0];
        #pragma unroll
        for (int e = 1; e < E; e++) if (nz[e] > v0) { v0 = nz[e]; i0 = e; }
        int i1 = -1; float v1 = -3.0e38f;
        #pragma unroll
        for (int e = 0; e < E; e++) if (e != i0 && nz[e] > v1) { v1 = nz[e]; i1 = e; }

        const float ex = expf(v1 - v0);
        const float inv = 1.f / (1.f + ex);

        const int p0 = atomicAdd(&g_cnt[i0], 1);
        const int p1 = atomicAdd(&g_cnt[i1], 1);
        const int r0 = i0 * T + p0;
        const int r1 = i1 * T + p1;
        g_tok[r0] = warp;
        g_tok[r1] = warp;
        g_rowof[2 * warp]     = r0;
        g_rowof[2 * warp + 1] = r1;
        g_w[2 * warp]     = inv;
        g_w[2 * warp + 1] = ex * inv;
    }
}

// ---------------------------------------------------------------------------
// helpers
// ---------------------------------------------------------------------------
__device__ __forceinline__ uint32_t smem_u32(const void* p) {
    return (uint32_t)__cvta_generic_to_shared(p);
}
__device__ __forceinline__ void cp16(uint32_t dst, const void* src) {
    asm volatile("cp.async.cg.shared.global [%0], [%1], 16;"
                 :: "r"(dst), "l"(src) : "memory");
}
__device__ __forceinline__ void cp_commit() {
    asm volatile("cp.async.commit_group;" ::: "memory");
}
template <int N>
__device__ __forceinline__ void cp_wait() {
    asm volatile("cp.async.wait_group %0;" :: "n"(N) : "memory");
}
__device__ __forceinline__ void ldsm4(uint32_t& r0, uint32_t& r1, uint32_t& r2, uint32_t& r3,
                                      uint32_t addr) {
    asm volatile("ldmatrix.sync.aligned.m8n8.x4.shared.b16 {%0,%1,%2,%3}, [%4];"
                 : "=r"(r0), "=r"(r1), "=r"(r2), "=r"(r3) : "r"(addr));
}
__device__ __forceinline__ void mma_f16(float& c0, float& c1, float& c2, float& c3,
                                        uint32_t a0, uint32_t a1, uint32_t a2, uint32_t a3,
                                        uint32_t b0, uint32_t b1) {
    asm volatile(
        "mma.sync.aligned.m16n8k16.row.col.f32.f16.f16.f32 "
        "{%0,%1,%2,%3}, {%4,%5,%6,%7}, {%8,%9}, {%0,%1,%2,%3};"
        : "+f"(c0), "+f"(c1), "+f"(c2), "+f"(c3)
        : "r"(a0), "r"(a1), "r"(a2), "r"(a3), "r"(b0), "r"(b1));
}

// load one sub-k16 fragment set (A: 4 x ldsm.x4, B: 4 x ldsm.x4)
__device__ __forceinline__ void load_frags(uint32_t (&af)[4][4], uint32_t (&bf)[8][2],
                                           const uint32_t (&aAddr)[4],
                                           const uint32_t (&bAddr)[4], uint32_t off)
{
    #pragma unroll
    for (int mi = 0; mi < 4; mi++)
        ldsm4(af[mi][0], af[mi][1], af[mi][2], af[mi][3], aAddr[mi] + off);
    #pragma unroll
    for (int p = 0; p < 4; p++) {
        uint32_t r0, r1, r2, r3;
        ldsm4(r0, r1, r2, r3, bAddr[p] + off);
        bf[2 * p][0] = r0;     bf[2 * p][1] = r1;
        bf[2 * p + 1][0] = r2; bf[2 * p + 1][1] = r3;
    }
}

// 4x8 grid of m16n8k16 MMAs for one sub-k16
__device__ __forceinline__ void mma_tile(float (&acc)[4][8][4],
                                         const uint32_t (&af)[4][4],
                                         const uint32_t (&bf)[8][2])
{
    #pragma unroll
    for (int mi = 0; mi < 4; mi++)
        #pragma unroll
        for (int ni = 0; ni < 8; ni++)
            mma_f16(acc[mi][ni][0], acc[mi][ni][1], acc[mi][ni][2], acc[mi][ni][3],
                    af[mi][0], af[mi][1], af[mi][2], af[mi][3],
                    bf[ni][0], bf[ni][1]);
}

// ---------------------------------------------------------------------------
// Grouped fp16 tensor-core GEMM. 128x256 tile, 64x64 warp tiles, BK=32,
// 3-stage cp.async pipeline with software-pipelined fragments:
//   LDSM(kt,sub1); cp.async(kt+2); MMA(sub0); wait+sync; LDSM(kt+1,sub0); MMA(sub1)
//   MODE 0: H = relu(gather(xh) @ W1h[e]^T + b1);   K=768,  N=3072, out fp16
//   MODE 1: Y = Hh @ W2h[e]^T (+b2 on split 0);     K=768/split x4, N=768, fp32
// ---------------------------------------------------------------------------
template <int MODE>
__global__ __launch_bounds__(256, 1)
void gemm_f16_kernel(const __half* __restrict__ Wh,
                     const float* __restrict__ bias)
{
    constexpr int KROW = (MODE == 0) ? D : DFF;      // row stride of A and W
    constexpr int NTOT = (MODE == 0) ? DFF : D;
    constexpr int KLEN = (MODE == 0) ? D : (DFF / SPLITK);
    constexpr int NKT  = KLEN / BK;

    extern __shared__ __half sm[];

    int e, sK;
    if (MODE == 0) { e = blockIdx.z; sK = 0; }
    else           { e = blockIdx.z & (E - 1); sK = blockIdx.z >> 3; }
    const int ks0 = (MODE == 1) ? sK * KLEN : 0;

    const int cnt = g_cnt[e];
    const int m0  = blockIdx.y * BM;
    if (m0 >= cnt) return;
    const int n0  = blockIdx.x * BN;

    const int tid  = threadIdx.x;
    const int lane = tid & 31;
    const int warp = tid >> 5;
    const int wm   = warp >> 2;        // 0..1  (64-row slices)
    const int wn   = warp & 3;         // 0..3  (64-col slices)
    const int g    = lane >> 2;
    const int q    = lane & 3;

    // ---- staging: 384 rows x 32 halves; 1536 16B-chunks; 6 per thread ----
    const __half* src[6];
    uint32_t      stA[6];
    const uint32_t smb = smem_u32(sm);
    #pragma unroll
    for (int k = 0; k < 6; k++) {
        const int c   = tid + 256 * k;
        const int rc  = c >> 2;
        const int cc8 = (c & 3) * 8;
        stA[k] = smb + (uint32_t)(rc * SA + cc8) * 2;
        if (rc < BM) {
            const int am = m0 + rc;
            if (MODE == 0) {
                const int tok = (am < cnt) ? g_tok[e * T + am] : 0;
                src[k] = g_xh + (size_t)tok * KROW + cc8;
            } else {
                const int r = (am < cnt) ? am : 0;
                src[k] = g_Hh + ((size_t)e * T + r) * KROW + ks0 + cc8;
            }
        } else {
            src[k] = Wh + ((size_t)e * NTOT + n0 + (rc - BM)) * KROW + ks0 + cc8;
        }
    }

    // ---- ldmatrix lane base addresses (stage 0, sub-k 0) ----
    uint32_t aAddr[4], bAddr[4];
    {
        const int rin = lane & 15;
        const int ch  = lane >> 4;
        #pragma unroll
        for (int mi = 0; mi < 4; mi++)
            aAddr[mi] = smb + (uint32_t)((wm * 64 + mi * 16 + rin) * SA + ch * 8) * 2;
    }
    {
        const int rin = ((lane >> 4) << 3) + (lane & 7);
        const int ch  = (lane >> 3) & 1;
        #pragma unroll
        for (int p = 0; p < 4; p++)
            bAddr[p] = smb + (uint32_t)((BM + wn * 64 + p * 16 + rin) * SA + ch * 8) * 2;
    }

    float acc[4][8][4];
    #pragma unroll
    for (int mi = 0; mi < 4; mi++)
        #pragma unroll
        for (int ni = 0; ni < 8; ni++)
            #pragma unroll
            for (int r = 0; r < 4; r++) acc[mi][ni][r] = 0.f;

    // prologue: fill stages 0..1
    #pragma unroll
    for (int s = 0; s < STAGES - 1; s++) {
        #pragma unroll
        for (int k = 0; k < 6; k++)
            cp16(stA[k] + s * STG_BYTES, src[k] + s * BK);
        cp_commit();
    }
    cp_wait<1>();                      // stage 0 complete
    __syncthreads();

    uint32_t af0[4][4], bf0[8][2], af1[4][4], bf1[8][2];
    load_frags(af0, bf0, aAddr, bAddr, 0);   // (kt=0, sub0)

    int cur = 0;
    for (int kt = 0; kt < NKT; kt++) {
        const uint32_t soff = (uint32_t)(cur * STG_BYTES);

        // 1) LDSM (kt, sub1) — overlapped by MMA(sub0) below
        load_frags(af1, bf1, aAddr, bAddr, soff + 32);

        // 2) issue cp.async for stage kt+2 (buffer freed by last sync)
        if (kt + STAGES - 1 < NKT) {
            int tgt = cur + 2; if (tgt >= STAGES) tgt -= STAGES;
            const int ko = (kt + STAGES - 1) * BK;
            #pragma unroll
            for (int k = 0; k < 6; k++)
                cp16(stA[k] + tgt * STG_BYTES, src[k] + ko);
        }
        cp_commit();

        // 3) MMA sub0
        mma_tile(acc, af0, bf0);

        // 4) stage kt+1 complete; buffers safe to rotate
        cp_wait<1>();
        __syncthreads();

        // 5) LDSM (kt+1, sub0) — overlapped by MMA(sub1) below
        int nxt = cur + 1; if (nxt >= STAGES) nxt = 0;
        if (kt + 1 < NKT)
            load_frags(af0, bf0, aAddr, bAddr, (uint32_t)(nxt * STG_BYTES));

        // 6) MMA sub1
        mma_tile(acc, af1, bf1);

        cur = nxt;
    }

    // ---- epilogue ----
    const float* be = bias + (size_t)e * NTOT;
    if (MODE == 0) {
        __half* Cb = g_Hh + (size_t)e * T * NTOT;
        #pragma unroll
        for (int mi = 0; mi < 4; mi++) {
            #pragma unroll
            for (int hh = 0; hh < 2; hh++) {
                const int m = m0 + wm * 64 + mi * 16 + g + hh * 8;
                if (m < cnt) {
                    __half* cr = Cb + (size_t)m * NTOT;
                    #pragma unroll
                    for (int ni = 0; ni < 8; ni++) {
                        const int c = n0 + wn * 64 + ni * 8 + 2 * q;
                        float v0 = acc[mi][ni][2 * hh]     + be[c];
                        float v1 = acc[mi][ni][2 * hh + 1] + be[c + 1];
                        v0 = fmaxf(v0, 0.f); v1 = fmaxf(v1, 0.f);
                        *reinterpret_cast<__half2*>(cr + c) = __floats2half2_rn(v0, v1);
                    }
                }
            }
        }
    } else {
        float* Cb = g_Y[sK] + (size_t)e * T * NTOT;
        #pragma unroll
        for (int mi = 0; mi < 4; mi++) {
            #pragma unroll
            for (int hh = 0; hh < 2; hh++) {
                const int m = m0 + wm * 64 + mi * 16 + g + hh * 8;
                if (m < cnt) {
                    float* cr = Cb + (size_t)m * NTOT;
                    #pragma unroll
                    for (int ni = 0; ni < 8; ni++) {
                        const int c = n0 + wn * 64 + ni * 8 + 2 * q;
                        float v0 = acc[mi][ni][2 * hh];
                        float v1 = acc[mi][ni][2 * hh + 1];
                        if (sK == 0) { v0 += be[c]; v1 += be[c + 1]; }
                        *reinterpret_cast<float2*>(cr + c) = make_float2(v0, v1);
                    }
                }
            }
        }
    }
}

// ---------------------------------------------------------------------------
// Combine (deterministic): out[t] = w0*sum_s Ys[r0] + w1*sum_s Ys[r1]
// ---------------------------------------------------------------------------
__global__ void combine_kernel(float* __restrict__ out)
{
    const int t = blockIdx.x;
    const int j = threadIdx.x;            // 0..191
    const int r0 = g_rowof[2 * t];
    const int r1 = g_rowof[2 * t + 1];
    const float w0 = g_w[2 * t];
    const float w1 = g_w[2 * t + 1];
    float4 sa = make_float4(0.f, 0.f, 0.f, 0.f);
    float4 sb = make_float4(0.f, 0.f, 0.f, 0.f);
    #pragma unroll
    for (int s = 0; s < SPLITK; s++) {
        const float4 a = reinterpret_cast<const float4*>(g_Y[s] + (size_t)r0 * D)[j];
        const float4 b = reinterpret_cast<const float4*>(g_Y[s] + (size_t)r1 * D)[j];
        sa.x += a.x; sa.y += a.y; sa.z += a.z; sa.w += a.w;
        sb.x += b.x; sb.y += b.y; sb.z += b.z; sb.w += b.w;
    }
    float4 o;
    o.x = fmaf(w0, sa.x, w1 * sb.x);
    o.y = fmaf(w0, sa.y, w1 * sb.y);
    o.z = fmaf(w0, sa.z, w1 * sb.z);
    o.w = fmaf(w0, sa.w, w1 * sb.w);
    reinterpret_cast<float4*>(out + (size_t)t * D)[j] = o;
}

// ---------------------------------------------------------------------------
// Launch
// ---------------------------------------------------------------------------
extern "C" void kernel_launch(void* const* d_in, const int* in_sizes, int n_in,
                              void* d_out, int out_size)
{
    const float* x     = (const float*)d_in[0];
    const float* noise = (const float*)d_in[1];
    const float* Wg    = (const float*)d_in[2];
    const float* bg    = (const float*)d_in[3];
    const float* Wn    = (const float*)d_in[4];
    const float* bn    = (const float*)d_in[5];
    const float* W1    = (const float*)d_in[6];
    const float* b1    = (const float*)d_in[7];
    const float* W2    = (const float*)d_in[8];
    const float* b2    = (const float*)d_in[9];
    float* out = (float*)d_out;

    cudaFuncSetAttribute(gemm_f16_kernel<0>,
                         cudaFuncAttributeMaxDynamicSharedMemorySize, SMEM_TOT);
    cudaFuncSetAttribute(gemm_f16_kernel<1>,
                         cudaFuncAttributeMaxDynamicSharedMemorySize, SMEM_TOT);

    reset_kernel<<<1, 32>>>();

    // fp32 -> fp16 conversions (x, W1, W2) in one launch
    {
        __half* xh;  cudaGetSymbolAddress((void**)&xh,  g_xh);
        __half* w1h; cudaGetSymbolAddress((void**)&w1h, g_W1h);
        __half* w2h; cudaGetSymbolAddress((void**)&w2h, g_W2h);
        const int nx8 = T * D / 8;
        const int nw8 = E * DFF * D / 8;
        const int tot = nx8 + 2 * nw8;
        cvt3_kernel<<<(tot + 255) / 256, 256>>>(x, W1, W2, xh, w1h, w2h, nx8, nw8);
    }

    router_kernel<<<T / 8, 256>>>(x, noise, Wg, bg, Wn, bn);

    // GEMM1: H = relu(xh_gathered @ W1h[e]^T + b1[e])   N=3072, K=768
    {
        __half* w1h; cudaGetSymbolAddress((void**)&w1h, g_W1h);
        dim3 grid(DFF / BN, T / BM, E);
        gemm_f16_kernel<0><<<grid, 256, SMEM_TOT>>>(w1h, b1);
    }
    // GEMM2: Y = Hh @ W2h[e]^T + b2[e], split-K=4       N=768, K=3072
    {
        __half* w2h; cudaGetSymbolAddress((void**)&w2h, g_W2h);
        dim3 grid(D / BN, T / BM, SPLITK * E);
        gemm_f16_kernel<1><<<grid, 256, SMEM_TOT>>>(w2h, b2);
    }

    combine_kernel<<<T, D / 4>>>(out);
}

// round 10
// speedup vs baseline: 5.8626x; 1.0594x over previous
#include <cuda_runtime.h>
#include <cuda_fp16.h>
#include <math.h>
#include <stdint.h>

// Problem constants: B=2, S=1024 -> T=2048 tokens; D=768; E=8 experts; DFF=3072; top-2.
#define T    2048
#define D    768
#define E    8
#define DFF  3072

// GEMM tiling: 128x256 CTA tile, BK=64 (4 x k16 sub-steps per sync), 8 warps
// (2x4), 64x64 warp tiles, fp16 mma.sync m16n8k16 + ldmatrix, 3-stage cp.async,
// software-pipelined fragment double-buffering.
#define BM 128
#define BN 256
#define BK 64
#define SA 72                       // smem row stride (halves): 64 + 8 pad
#define STAGES 3
#define STG_ROWS (BM + BN)          // 384 rows (A then B) per stage
#define STG_BYTES (STG_ROWS * SA * 2)   // 55296 B per stage
#define SMEM_TOT (STAGES * STG_BYTES)   // 165888 B
#define SPLITK 4

// ---------------------------------------------------------------------------
// Device scratch
// ---------------------------------------------------------------------------
__device__ int    g_cnt[E];
__device__ int    g_tok[E * T];
__device__ int    g_rowof[T * 2];
__device__ float  g_w[T * 2];
__device__ __half g_xh[T * D];                    // x in fp16
__device__ __half g_W1h[(size_t)E * DFF * D];     // W1 in fp16
__device__ __half g_W2h[(size_t)E * D * DFF];     // W2 in fp16
__device__ __half g_Hh[(size_t)E * T * DFF];      // hidden acts, fp16
__device__ float  g_Y[SPLITK][E * T * D];         // split-K partial outputs

__global__ void reset_kernel() {
    if (threadIdx.x < E) g_cnt[threadIdx.x] = 0;
}

// ---------------------------------------------------------------------------
// fp32 -> fp16 conversion for x, W1, W2 in one launch (8 elems / thread)
// ---------------------------------------------------------------------------
__device__ __forceinline__ uint4 pack8(float4 a, float4 b) {
    __half2 h0 = __floats2half2_rn(a.x, a.y);
    __half2 h1 = __floats2half2_rn(a.z, a.w);
    __half2 h2 = __floats2half2_rn(b.x, b.y);
    __half2 h3 = __floats2half2_rn(b.z, b.w);
    uint4 u;
    u.x = *reinterpret_cast<uint32_t*>(&h0);
    u.y = *reinterpret_cast<uint32_t*>(&h1);
    u.z = *reinterpret_cast<uint32_t*>(&h2);
    u.w = *reinterpret_cast<uint32_t*>(&h3);
    return u;
}

__global__ void cvt3_kernel(const float* __restrict__ x,
                            const float* __restrict__ W1,
                            const float* __restrict__ W2,
                            __half* __restrict__ xh,
                            __half* __restrict__ w1h,
                            __half* __restrict__ w2h,
                            int nx8, int nw8)
{
    const int i = blockIdx.x * blockDim.x + threadIdx.x;
    const float* src; __half* dst; int j;
    if (i < nx8)            { src = x;  dst = xh;  j = i; }
    else if (i < nx8 + nw8) { src = W1; dst = w1h; j = i - nx8; }
    else if (i < nx8 + 2 * nw8) { src = W2; dst = w2h; j = i - nx8 - nw8; }
    else return;
    const float4 a = reinterpret_cast<const float4*>(src)[2 * j];
    const float4 b = reinterpret_cast<const float4*>(src)[2 * j + 1];
    reinterpret_cast<uint4*>(dst)[j] = pack8(a, b);
}

// ---------------------------------------------------------------------------
// Router: one warp per token, noisy top-2 gating + atomic per-expert
// compaction. Row values are position-invariant -> deterministic output.
// ---------------------------------------------------------------------------
__global__ void router_kernel(const float* __restrict__ x,
                              const float* __restrict__ noise,
                              const float* __restrict__ Wg,
                              const float* __restrict__ bg,
                              const float* __restrict__ Wn,
                              const float* __restrict__ bn)
{
    const int warp = (blockIdx.x * blockDim.x + threadIdx.x) >> 5;
    const int lane = threadIdx.x & 31;
    if (warp >= T) return;

    const float* xr = x + (size_t)warp * D;
    float xv[D / 32];
    #pragma unroll
    for (int i = 0; i < D / 32; i++) xv[i] = xr[lane + 32 * i];

    float nz[E];
    #pragma unroll
    for (int e = 0; e < E; e++) {
        const float* g  = Wg + e * D;
        const float* nw = Wn + e * D;
        float s1 = 0.f, s2 = 0.f;
        #pragma unroll
        for (int i = 0; i < D / 32; i++) {
            const float xi = xv[i];
            s1 = fmaf(xi, g[lane + 32 * i], s1);
            s2 = fmaf(xi, nw[lane + 32 * i], s2);
        }
        #pragma unroll
        for (int off = 16; off; off >>= 1) {
            s1 += __shfl_xor_sync(0xffffffffu, s1, off);
            s2 += __shfl_xor_sync(0xffffffffu, s2, off);
        }
        const float logit = s1 + bg[e];
        const float nlog  = s2 + bn[e];
        const float sp = fmaxf(nlog, 0.f) + log1pf(expf(-fabsf(nlog)));
        nz[e] = logit + noise[warp * E + e] * sp;
    }

    if (lane == 0) {
        int i0 = 0; float v0 = nz[0];
        #pragma unroll
        for (int e = 1; e < E; e++) if (nz[e] > v0) { v0 = nz[e]; i0 = e; }
        int i1 = -1; float v1 = -3.0e38f;
        #pragma unroll
        for (int e = 0; e < E; e++) if (e != i0 && nz[e] > v1) { v1 = nz[e]; i1 = e; }

        const float ex = expf(v1 - v0);
        const float inv = 1.f / (1.f + ex);

        const int p0 = atomicAdd(&g_cnt[i0], 1);
        const int p1 = atomicAdd(&g_cnt[i1], 1);
        const int r0 = i0 * T + p0;
        const int r1 = i1 * T + p1;
        g_tok[r0] = warp;
        g_tok[r1] = warp;
        g_rowof[2 * warp]     = r0;
        g_rowof[2 * warp + 1] = r1;
        g_w[2 * warp]     = inv;
        g_w[2 * warp + 1] = ex * inv;
    }
}

// ---------------------------------------------------------------------------
// helpers
// ---------------------------------------------------------------------------
__device__ __forceinline__ uint32_t smem_u32(const void* p) {
    return (uint32_t)__cvta_generic_to_shared(p);
}
__device__ __forceinline__ void cp16(uint32_t dst, const void* src) {
    asm volatile("cp.async.cg.shared.global [%0], [%1], 16;"
                 :: "r"(dst), "l"(src) : "memory");
}
__device__ __forceinline__ void cp_commit() {
    asm volatile("cp.async.commit_group;" ::: "memory");
}
template <int N>
__device__ __forceinline__ void cp_wait() {
    asm volatile("cp.async.wait_group %0;" :: "n"(N) : "memory");
}
__device__ __forceinline__ void ldsm4(uint32_t& r0, uint32_t& r1, uint32_t& r2, uint32_t& r3,
                                      uint32_t addr) {
    asm volatile("ldmatrix.sync.aligned.m8n8.x4.shared.b16 {%0,%1,%2,%3}, [%4];"
                 : "=r"(r0), "=r"(r1), "=r"(r2), "=r"(r3) : "r"(addr));
}
__device__ __forceinline__ void mma_f16(float& c0, float& c1, float& c2, float& c3,
                                        uint32_t a0, uint32_t a1, uint32_t a2, uint32_t a3,
                                        uint32_t b0, uint32_t b1) {
    asm volatile(
        "mma.sync.aligned.m16n8k16.row.col.f32.f16.f16.f32 "
        "{%0,%1,%2,%3}, {%4,%5,%6,%7}, {%8,%9}, {%0,%1,%2,%3};"
        : "+f"(c0), "+f"(c1), "+f"(c2), "+f"(c3)
        : "r"(a0), "r"(a1), "r"(a2), "r"(a3), "r"(b0), "r"(b1));
}

// load one sub-k16 fragment set (A: 4 x ldsm.x4, B: 4 x ldsm.x4)
__device__ __forceinline__ void load_frags(uint32_t (&af)[4][4], uint32_t (&bf)[8][2],
                                           const uint32_t (&aAddr)[4],
                                           const uint32_t (&bAddr)[4], uint32_t off)
{
    #pragma unroll
    for (int mi = 0; mi < 4; mi++)
        ldsm4(af[mi][0], af[mi][1], af[mi][2], af[mi][3], aAddr[mi] + off);
    #pragma unroll
    for (int p = 0; p < 4; p++) {
        uint32_t r0, r1, r2, r3;
        ldsm4(r0, r1, r2, r3, bAddr[p] + off);
        bf[2 * p][0] = r0;     bf[2 * p][1] = r1;
        bf[2 * p + 1][0] = r2; bf[2 * p + 1][1] = r3;
    }
}

// 4x8 grid of m16n8k16 MMAs for one sub-k16
__device__ __forceinline__ void mma_tile(float (&acc)[4][8][4],
                                         const uint32_t (&af)[4][4],
                                         const uint32_t (&bf)[8][2])
{
    #pragma unroll
    for (int mi = 0; mi < 4; mi++)
        #pragma unroll
        for (int ni = 0; ni < 8; ni++)
            mma_f16(acc[mi][ni][0], acc[mi][ni][1], acc[mi][ni][2], acc[mi][ni][3],
                    af[mi][0], af[mi][1], af[mi][2], af[mi][3],
                    bf[ni][0], bf[ni][1]);
}

// ---------------------------------------------------------------------------
// Grouped fp16 tensor-core GEMM. 128x256 tile, 64x64 warp tiles, BK=64
// (4 sub-k16 per sync), 3-stage cp.async pipeline, pipelined fragments.
//   MODE 0: H = relu(gather(xh) @ W1h[e]^T + b1);   K=768,  N=3072, out fp16
//   MODE 1: Y = Hh @ W2h[e]^T (+b2 on split 0);     K=768/split x4, N=768, fp32
// ---------------------------------------------------------------------------
template <int MODE>
__global__ __launch_bounds__(256, 1)
void gemm_f16_kernel(const __half* __restrict__ Wh,
                     const float* __restrict__ bias)
{
    constexpr int KROW = (MODE == 0) ? D : DFF;      // row stride of A and W
    constexpr int NTOT = (MODE == 0) ? DFF : D;
    constexpr int KLEN = (MODE == 0) ? D : (DFF / SPLITK);
    constexpr int NKT  = KLEN / BK;

    extern __shared__ __half sm[];

    int e, sK;
    if (MODE == 0) { e = blockIdx.z; sK = 0; }
    else           { e = blockIdx.z & (E - 1); sK = blockIdx.z >> 3; }
    const int ks0 = (MODE == 1) ? sK * KLEN : 0;

    const int cnt = g_cnt[e];
    const int m0  = blockIdx.y * BM;
    if (m0 >= cnt) return;
    const int n0  = blockIdx.x * BN;

    const int tid  = threadIdx.x;
    const int lane = tid & 31;
    const int warp = tid >> 5;
    const int wm   = warp >> 2;        // 0..1  (64-row slices)
    const int wn   = warp & 3;         // 0..3  (64-col slices)
    const int g    = lane >> 2;
    const int q    = lane & 3;

    // ---- staging: 384 rows x 64 halves = 3072 16B-chunks; 12 per thread.
    // chunk c = tid + 256k -> row (tid>>3)+32k, col chunk (tid&7)*8 (k-invariant).
    // k=0..3 -> A region (gathered rows), k=4..11 -> B region (rows r8+32*(k-4)).
    const int r8 = tid >> 3;
    const int c8 = (tid & 7) * 8;
    const uint32_t smb = smem_u32(sm);
    const uint32_t st0 = smb + (uint32_t)(r8 * SA + c8) * 2;   // k stride: 32*SA*2 B

    const __half* srcA[4];
    #pragma unroll
    for (int k = 0; k < 4; k++) {
        const int am = m0 + r8 + 32 * k;
        if (MODE == 0) {
            const int tok = (am < cnt) ? g_tok[e * T + am] : 0;
            srcA[k] = g_xh + (size_t)tok * KROW + c8;
        } else {
            const int r = (am < cnt) ? am : 0;
            srcA[k] = g_Hh + ((size_t)e * T + r) * KROW + ks0 + c8;
        }
    }
    const __half* srcB = Wh + ((size_t)e * NTOT + n0 + r8) * KROW + ks0 + c8;

    // ---- ldmatrix lane base addresses (stage 0, sub-k 0) ----
    uint32_t aAddr[4], bAddr[4];
    {
        const int rin = lane & 15;
        const int ch  = lane >> 4;
        #pragma unroll
        for (int mi = 0; mi < 4; mi++)
            aAddr[mi] = smb + (uint32_t)((wm * 64 + mi * 16 + rin) * SA + ch * 8) * 2;
    }
    {
        const int rin = ((lane >> 4) << 3) + (lane & 7);
        const int ch  = (lane >> 3) & 1;
        #pragma unroll
        for (int p = 0; p < 4; p++)
            bAddr[p] = smb + (uint32_t)((BM + wn * 64 + p * 16 + rin) * SA + ch * 8) * 2;
    }

    float acc[4][8][4];
    #pragma unroll
    for (int mi = 0; mi < 4; mi++)
        #pragma unroll
        for (int ni = 0; ni < 8; ni++)
            #pragma unroll
            for (int r = 0; r < 4; r++) acc[mi][ni][r] = 0.f;

    // stage-fill helper (12 cp16 per thread)
    auto FILL = [&](int stage, int kt) {
        const uint32_t so = (uint32_t)(stage * STG_BYTES);
        const int ko = kt * BK;
        #pragma unroll
        for (int k = 0; k < 4; k++)
            cp16(st0 + so + k * (32 * SA * 2), srcA[k] + ko);
        #pragma unroll
        for (int k = 0; k < 8; k++)
            cp16(st0 + so + (k + 4) * (32 * SA * 2), srcB + (size_t)(32 * k) * KROW + ko);
    };

    // prologue: fill stages 0..1
    #pragma unroll
    for (int s = 0; s < STAGES - 1; s++) { FILL(s, s); cp_commit(); }
    cp_wait<1>();                      // stage 0 complete
    __syncthreads();

    uint32_t af0[4][4], bf0[8][2], af1[4][4], bf1[8][2];
    load_frags(af0, bf0, aAddr, bAddr, 0);   // (kt=0, sub0)

    int cur = 0;
    for (int kt = 0; kt < NKT; kt++) {
        const uint32_t soff = (uint32_t)(cur * STG_BYTES);

        // sub1 frags, then next-stage cp.async, all under MMA(sub0)
        load_frags(af1, bf1, aAddr, bAddr, soff + 32);
        if (kt + STAGES - 1 < NKT) {
            int tgt = cur + 2; if (tgt >= STAGES) tgt -= STAGES;
            FILL(tgt, kt + STAGES - 1);
        }
        cp_commit();
        mma_tile(acc, af0, bf0);                       // sub0

        load_frags(af0, bf0, aAddr, bAddr, soff + 64); // sub2 frags
        mma_tile(acc, af1, bf1);                       // sub1

        load_frags(af1, bf1, aAddr, bAddr, soff + 96); // sub3 frags
        mma_tile(acc, af0, bf0);                       // sub2

        cp_wait<1>();                   // stage kt+1 complete
        __syncthreads();                // barrier drains under sub2's MMAs

        int nxt = cur + 1; if (nxt >= STAGES) nxt = 0;
        if (kt + 1 < NKT)               // (kt+1, sub0) frags under MMA(sub3)
            load_frags(af0, bf0, aAddr, bAddr, (uint32_t)(nxt * STG_BYTES));
        mma_tile(acc, af1, bf1);                       // sub3

        cur = nxt;
    }

    // ---- epilogue ----
    const float* be = bias + (size_t)e * NTOT;
    if (MODE == 0) {
        __half* Cb = g_Hh + (size_t)e * T * NTOT;
        #pragma unroll
        for (int mi = 0; mi < 4; mi++) {
            #pragma unroll
            for (int hh = 0; hh < 2; hh++) {
                const int m = m0 + wm * 64 + mi * 16 + g + hh * 8;
                if (m < cnt) {
                    __half* cr = Cb + (size_t)m * NTOT;
                    #pragma unroll
                    for (int ni = 0; ni < 8; ni++) {
                        const int c = n0 + wn * 64 + ni * 8 + 2 * q;
                        float v0 = acc[mi][ni][2 * hh]     + be[c];
                        float v1 = acc[mi][ni][2 * hh + 1] + be[c + 1];
                        v0 = fmaxf(v0, 0.f); v1 = fmaxf(v1, 0.f);
                        *reinterpret_cast<__half2*>(cr + c) = __floats2half2_rn(v0, v1);
                    }
                }
            }
        }
    } else {
        float* Cb = g_Y[sK] + (size_t)e * T * NTOT;
        #pragma unroll
        for (int mi = 0; mi < 4; mi++) {
            #pragma unroll
            for (int hh = 0; hh < 2; hh++) {
                const int m = m0 + wm * 64 + mi * 16 + g + hh * 8;
                if (m < cnt) {
                    float* cr = Cb + (size_t)m * NTOT;
                    #pragma unroll
                    for (int ni = 0; ni < 8; ni++) {
                        const int c = n0 + wn * 64 + ni * 8 + 2 * q;
                        float v0 = acc[mi][ni][2 * hh];
                        float v1 = acc[mi][ni][2 * hh + 1];
                        if (sK == 0) { v0 += be[c]; v1 += be[c + 1]; }
                        *reinterpret_cast<float2*>(cr + c) = make_float2(v0, v1);
                    }
                }
            }
        }
    }
}

// ---------------------------------------------------------------------------
// Combine (deterministic): out[t] = w0*sum_s Ys[r0] + w1*sum_s Ys[r1]
// ---------------------------------------------------------------------------
__global__ void combine_kernel(float* __restrict__ out)
{
    const int t = blockIdx.x;
    const int j = threadIdx.x;            // 0..191
    const int r0 = g_rowof[2 * t];
    const int r1 = g_rowof[2 * t + 1];
    const float w0 = g_w[2 * t];
    const float w1 = g_w[2 * t + 1];
    float4 sa = make_float4(0.f, 0.f, 0.f, 0.f);
    float4 sb = make_float4(0.f, 0.f, 0.f, 0.f);
    #pragma unroll
    for (int s = 0; s < SPLITK; s++) {
        const float4 a = reinterpret_cast<const float4*>(g_Y[s] + (size_t)r0 * D)[j];
        const float4 b = reinterpret_cast<const float4*>(g_Y[s] + (size_t)r1 * D)[j];
        sa.x += a.x; sa.y += a.y; sa.z += a.z; sa.w += a.w;
        sb.x += b.x; sb.y += b.y; sb.z += b.z; sb.w += b.w;
    }
    float4 o;
    o.x = fmaf(w0, sa.x, w1 * sb.x);
    o.y = fmaf(w0, sa.y, w1 * sb.y);
    o.z = fmaf(w0, sa.z, w1 * sb.z);
    o.w = fmaf(w0, sa.w, w1 * sb.w);
    reinterpret_cast<float4*>(out + (size_t)t * D)[j] = o;
}

// ---------------------------------------------------------------------------
// Launch
// ---------------------------------------------------------------------------
extern "C" void kernel_launch(void* const* d_in, const int* in_sizes, int n_in,
                              void* d_out, int out_size)
{
    const float* x     = (const float*)d_in[0];
    const float* noise = (const float*)d_in[1];
    const float* Wg    = (const float*)d_in[2];
    const float* bg    = (const float*)d_in[3];
    const float* Wn    = (const float*)d_in[4];
    const float* bn    = (const float*)d_in[5];
    const float* W1    = (const float*)d_in[6];
    const float* b1    = (const float*)d_in[7];
    const float* W2    = (const float*)d_in[8];
    const float* b2    = (const float*)d_in[9];
    float* out = (float*)d_out;

    cudaFuncSetAttribute(gemm_f16_kernel<0>,
                         cudaFuncAttributeMaxDynamicSharedMemorySize, SMEM_TOT);
    cudaFuncSetAttribute(gemm_f16_kernel<1>,
                         cudaFuncAttributeMaxDynamicSharedMemorySize, SMEM_TOT);

    reset_kernel<<<1, 32>>>();

    // fp32 -> fp16 conversions (x, W1, W2) in one launch
    {
        __half* xh;  cudaGetSymbolAddress((void**)&xh,  g_xh);
        __half* w1h; cudaGetSymbolAddress((void**)&w1h, g_W1h);
        __half* w2h; cudaGetSymbolAddress((void**)&w2h, g_W2h);
        const int nx8 = T * D / 8;
        const int nw8 = E * DFF * D / 8;
        const int tot = nx8 + 2 * nw8;
        cvt3_kernel<<<(tot + 255) / 256, 256>>>(x, W1, W2, xh, w1h, w2h, nx8, nw8);
    }

    router_kernel<<<T / 8, 256>>>(x, noise, Wg, bg, Wn, bn);

    // GEMM1: H = relu(xh_gathered @ W1h[e]^T + b1[e])   N=3072, K=768
    {
        __half* w1h; cudaGetSymbolAddress((void**)&w1h, g_W1h);
        dim3 grid(DFF / BN, T / BM, E);
        gemm_f16_kernel<0><<<grid, 256, SMEM_TOT>>>(w1h, b1);
    }
    // GEMM2: Y = Hh @ W2h[e]^T + b2[e], split-K=4       N=768, K=3072
    {
        __half* w2h; cudaGetSymbolAddress((void**)&w2h, g_W2h);
        dim3 grid(D / BN, T / BM, SPLITK * E);
        gemm_f16_kernel<1><<<grid, 256, SMEM_TOT>>>(w2h, b2);
    }

    combine_kernel<<<T, D / 4>>>(out);
}